// round 1
// baseline (speedup 1.0000x reference)
#include <cuda_runtime.h>
#include <cuda_bf16.h>
#include <cstdint>

// Problem constants (static per reference)
#define NB   8
#define LQ   2048
#define C    256
#define M    8
#define L    4
#define P    4
#define DH   32
#define S    3840
#define NQ   (NB * LQ)          // 16384 total queries
#define MLP  (M * L * P)        // 128

__device__ __constant__ int   c_tlen[4]   = {2048, 1024, 512, 256};
__device__ __constant__ int   c_tstart[4] = {0, 2048, 3072, 3584};
__device__ __constant__ float c_invT[4]   = {1.0f/2048.0f, 1.0f/1024.0f, 1.0f/512.0f, 1.0f/256.0f};

// Scratch (device globals — no allocation allowed)
__device__ float g_value[NB * S * C];     // 31.5 MB : value = input_flatten @ W_val + b_val
__device__ float g_offattn[NQ * 256];     // 16.8 MB : [0:128)=off raw, [128:256)=attn raw per query
__device__ float g_deform[NQ * C];        // 16.8 MB : deform-core output before W_out

// ---------------------------------------------------------------------------
// SGEMM: C[r, c] = sum_k A[r, k] * B[k, c] + bias[c]
// A is row-major with lda = 256 (K fixed = 256). B row-major ldb. C row-major ldc.
// BM=BN=64, BK=16, 256 threads, 4x4 microtile per thread.
// ---------------------------------------------------------------------------
#define BM 64
#define BN 64
#define BK 16

__global__ __launch_bounds__(256) void sgemm_bias(
    const float* __restrict__ A, const float* __restrict__ B,
    const float* __restrict__ bias, float* __restrict__ Cm,
    int ldb, int ldc)
{
    __shared__ float As[BK][BM + 4];   // +4 pad: keeps 16B alignment, spreads banks
    __shared__ float Bs[BK][BN];

    const int tid  = threadIdx.x;
    const int row0 = blockIdx.y * BM;
    const int col0 = blockIdx.x * BN;
    const int tr   = (tid >> 4) << 2;   // 0..60 step 4
    const int tc   = (tid & 15) << 2;   // 0..60 step 4

    float acc[4][4] = {};

    for (int k0 = 0; k0 < 256; k0 += BK) {
        // Load A tile (64 rows x 16 k), each thread one float4 along k
        {
            int e  = tid << 2;
            int r  = e >> 4;       // 0..63
            int kk = e & 15;       // 0,4,8,12
            float4 v = *reinterpret_cast<const float4*>(
                A + (size_t)(row0 + r) * 256 + k0 + kk);
            As[kk + 0][r] = v.x; As[kk + 1][r] = v.y;
            As[kk + 2][r] = v.z; As[kk + 3][r] = v.w;
        }
        // Load B tile (16 k x 64 cols), each thread one float4 along cols
        {
            int e  = tid << 2;
            int kk = e >> 6;       // 0..15
            int cc = e & 63;       // 0..60 step 4
            float4 v = *reinterpret_cast<const float4*>(
                B + (size_t)(k0 + kk) * ldb + col0 + cc);
            *reinterpret_cast<float4*>(&Bs[kk][cc]) = v;
        }
        __syncthreads();

        #pragma unroll
        for (int kk = 0; kk < BK; kk++) {
            float a[4], b[4];
            #pragma unroll
            for (int i = 0; i < 4; i++) a[i] = As[kk][tr + i];
            #pragma unroll
            for (int j = 0; j < 4; j++) b[j] = Bs[kk][tc + j];
            #pragma unroll
            for (int i = 0; i < 4; i++)
                #pragma unroll
                for (int j = 0; j < 4; j++)
                    acc[i][j] = fmaf(a[i], b[j], acc[i][j]);
        }
        __syncthreads();
    }

    float4 bv = *reinterpret_cast<const float4*>(bias + col0 + tc);
    #pragma unroll
    for (int i = 0; i < 4; i++) {
        float4 o;
        o.x = acc[i][0] + bv.x;
        o.y = acc[i][1] + bv.y;
        o.z = acc[i][2] + bv.z;
        o.w = acc[i][3] + bv.w;
        *reinterpret_cast<float4*>(Cm + (size_t)(row0 + tr + i) * ldc + col0 + tc) = o;
    }
}

// ---------------------------------------------------------------------------
// Softmax over L*P=16 per (query, head), compute sampling locations,
// write loc + attn straight into the output buffer.
// One block (128 threads) per query.
// ---------------------------------------------------------------------------
__global__ __launch_bounds__(128) void softmax_loc_kernel(
    const float* __restrict__ refp,   // (N, LQ, L, 1)
    float* __restrict__ out_loc,      // (N, LQ, M, L, P)
    float* __restrict__ out_attn)     // (N, LQ, M, L, P)
{
    const int q = blockIdx.x;          // global query index n*LQ + lq
    const int t = threadIdx.x;         // 0..127 = m*16 + l*4 + p
    const int m = t >> 4;
    const int l = (t >> 2) & 3;

    __shared__ float sh[128];
    const float* row = g_offattn + (size_t)q * 256;

    float off  = row[t];
    float araw = row[128 + t];

    sh[t] = araw;
    __syncthreads();
    float mx = -1e30f;
    #pragma unroll
    for (int i = 0; i < 16; i++) mx = fmaxf(mx, sh[(m << 4) + i]);
    float e = __expf(araw - mx);
    __syncthreads();
    sh[t] = e;
    __syncthreads();
    float s = 0.0f;
    #pragma unroll
    for (int i = 0; i < 16; i++) s += sh[(m << 4) + i];

    float attn = e / s;
    float loc  = refp[(size_t)q * 4 + l] + off * c_invT[l];

    out_loc [(size_t)q * 128 + t] = loc;
    out_attn[(size_t)q * 128 + t] = attn;
}

// ---------------------------------------------------------------------------
// Deformable sampling core: for each (query, head) gather 16 bilinear samples
// from value and do the attn-weighted sum. One block (256 threads) per query:
// warp m handles head m, lane = channel d.
// ---------------------------------------------------------------------------
__global__ __launch_bounds__(256) void deform_kernel(
    const float* __restrict__ loc,    // (N, LQ, M, L, P)
    const float* __restrict__ attn)   // (N, LQ, M, L, P)
{
    const int q = blockIdx.x;          // n*LQ + lq
    const int n = q >> 11;             // / LQ
    const int t = threadIdx.x;
    const int m = t >> 5;
    const int d = t & 31;

    __shared__ float sLoc[128], sAttn[128];
    if (t < 128) {
        sLoc[t]  = loc [(size_t)q * 128 + t];
        sAttn[t] = attn[(size_t)q * 128 + t];
    }
    __syncthreads();

    const float* vbase = g_value + (size_t)n * S * C + m * DH + d;
    float acc = 0.0f;

    #pragma unroll
    for (int lp = 0; lp < 16; lp++) {
        const int l  = lp >> 2;
        const int Ti = c_tlen[l];
        const int st = c_tstart[l];

        float lv  = sLoc [(m << 4) + lp];
        float a   = sAttn[(m << 4) + lp];

        float pos  = lv * (float)Ti - 0.5f;
        float x0f  = floorf(pos);
        float frac = pos - x0f;
        int   x0   = (int)x0f;

        float w0 = (x0 >= 0 && x0 < Ti)         ? (1.0f - frac) : 0.0f;
        float w1 = (x0 + 1 >= 0 && x0 + 1 < Ti) ? frac          : 0.0f;

        int i0 = min(max(x0, 0), Ti - 1);
        int i1 = min(max(x0 + 1, 0), Ti - 1);

        float v0 = vbase[(size_t)(st + i0) * C];
        float v1 = vbase[(size_t)(st + i1) * C];
        acc = fmaf(a, fmaf(w0, v0, w1 * v1), acc);
    }

    g_deform[(size_t)q * C + t] = acc;
}

// ---------------------------------------------------------------------------
extern "C" void kernel_launch(void* const* d_in, const int* in_sizes, int n_in,
                              void* d_out, int out_size)
{
    const float* query  = (const float*)d_in[0];
    const float* refp   = (const float*)d_in[1];
    const float* inpf   = (const float*)d_in[2];
    // d_in[3] temporal_lens, d_in[4] level_start_index — static, hardcoded
    const float* W_off  = (const float*)d_in[5];
    const float* b_off  = (const float*)d_in[6];
    const float* W_attn = (const float*)d_in[7];
    const float* b_attn = (const float*)d_in[8];
    const float* W_val  = (const float*)d_in[9];
    const float* b_val  = (const float*)d_in[10];
    const float* W_out  = (const float*)d_in[11];
    const float* b_out  = (const float*)d_in[12];

    float* out      = (float*)d_out;                  // (N, LQ, C)
    float* out_loc  = out + (size_t)NQ * C;           // (N, LQ, M, L, P)
    float* out_attn = out_loc + (size_t)NQ * MLP;     // (N, LQ, M, L, P)

    // Resolve scratch symbol addresses (pure queries; no allocation, capture-safe)
    float *pValue, *pOffattn, *pDeform;
    cudaGetSymbolAddress((void**)&pValue,   g_value);
    cudaGetSymbolAddress((void**)&pOffattn, g_offattn);
    cudaGetSymbolAddress((void**)&pDeform,  g_deform);

    // 1) value = input_flatten @ W_val + b_val        (30720 x 256) @ (256 x 256)
    sgemm_bias<<<dim3(C / BN, (NB * S) / BM), 256>>>(inpf, W_val, b_val, pValue, 256, 256);

    // 2) off raw  = query @ W_off + b_off             (16384 x 256) @ (256 x 128)
    sgemm_bias<<<dim3(MLP / BN, NQ / BM), 256>>>(query, W_off, b_off, pOffattn, 128, 256);

    // 3) attn raw = query @ W_attn + b_attn
    sgemm_bias<<<dim3(MLP / BN, NQ / BM), 256>>>(query, W_attn, b_attn, pOffattn + 128, 128, 256);

    // 4) softmax + sampling locations -> out_loc / out_attn
    softmax_loc_kernel<<<NQ, 128>>>(refp, out_loc, out_attn);

    // 5) deformable gather + weighted sum -> g_deform
    deform_kernel<<<NQ, 256>>>(out_loc, out_attn);

    // 6) out = g_deform @ W_out + b_out               (16384 x 256) @ (256 x 256)
    sgemm_bias<<<dim3(C / BN, NQ / BM), 256>>>(pDeform, W_out, b_out, out, 256, 256);
}

// round 3
// speedup vs baseline: 1.6503x; 1.6503x over previous
#include <cuda_runtime.h>
#include <cuda_bf16.h>
#include <cstdint>

// Problem constants (static per reference)
#define NB   8
#define LQ   2048
#define C    256
#define M    8
#define L    4
#define P    4
#define DH   32
#define S    3840
#define NQ   (NB * LQ)          // 16384
#define MLP  (M * L * P)        // 128

__device__ __constant__ int   c_tlen[4]   = {2048, 1024, 512, 256};
__device__ __constant__ int   c_tstart[4] = {0, 2048, 3072, 3584};
__device__ __constant__ float c_invT[4]   = {1.0f/2048.0f, 1.0f/1024.0f, 1.0f/512.0f, 1.0f/256.0f};

// Scratch (device globals — no allocation allowed)
__device__ float g_value[NB * S * C];
__device__ float g_offattn[NQ * 256];     // [0:128)=off raw, [128:256)=attn raw
__device__ float g_deform[NQ * C];

// ===========================================================================
// Helpers
// ===========================================================================
__device__ __forceinline__ uint32_t smem_u32(const void* p) {
    uint32_t a;
    asm("{ .reg .u64 t; cvta.to.shared.u64 t, %1; cvt.u32.u64 %0, t; }" : "=r"(a) : "l"(p));
    return a;
}

__device__ __forceinline__ void ldm_x4(uint32_t* r, uint32_t addr) {
    asm volatile("ldmatrix.sync.aligned.m8n8.x4.shared.b16 {%0,%1,%2,%3}, [%4];"
                 : "=r"(r[0]), "=r"(r[1]), "=r"(r[2]), "=r"(r[3]) : "r"(addr));
}

__device__ __forceinline__ void mma16816(float* c, const uint32_t* a, uint32_t b0, uint32_t b1) {
    asm volatile("mma.sync.aligned.m16n8k16.row.col.f32.bf16.bf16.f32 "
                 "{%0,%1,%2,%3}, {%4,%5,%6,%7}, {%8,%9}, {%0,%1,%2,%3};"
                 : "+f"(c[0]), "+f"(c[1]), "+f"(c[2]), "+f"(c[3])
                 : "r"(a[0]), "r"(a[1]), "r"(a[2]), "r"(a[3]), "r"(b0), "r"(b1));
}

// Split fp32 -> bf16 hi + bf16 lo (packed pairs)
__device__ __forceinline__ void split4(float4 v, uint32_t& h0, uint32_t& h1,
                                       uint32_t& l0, uint32_t& l1) {
    __nv_bfloat16 a = __float2bfloat16_rn(v.x);
    __nv_bfloat16 b = __float2bfloat16_rn(v.y);
    __nv_bfloat16 c = __float2bfloat16_rn(v.z);
    __nv_bfloat16 d = __float2bfloat16_rn(v.w);
    __nv_bfloat162 H0 = __halves2bfloat162(a, b);
    __nv_bfloat162 H1 = __halves2bfloat162(c, d);
    __nv_bfloat162 L0 = __floats2bfloat162_rn(v.x - __bfloat162float(a), v.y - __bfloat162float(b));
    __nv_bfloat162 L1 = __floats2bfloat162_rn(v.z - __bfloat162float(c), v.w - __bfloat162float(d));
    h0 = *reinterpret_cast<uint32_t*>(&H0);
    h1 = *reinterpret_cast<uint32_t*>(&H1);
    l0 = *reinterpret_cast<uint32_t*>(&L0);
    l1 = *reinterpret_cast<uint32_t*>(&L1);
}

// ===========================================================================
// bf16-split tensor-core GEMM via mma.sync (compute_103-safe, no tcgen05).
// C[r,c] = sum_k A[r,k]*W[k,c] + bias[c].  A row-major lda=256 (K=256).
// Block tile 128x128, BK=32, 8 warps (2 m x 4 n), warp tile 64x32.
// 3 MMA terms: Ahi*Bhi + Ahi*Blo + Alo*Bhi, fp32 accumulate.
// Smem rows padded to 40 bf16 (80 B) for conflict-free ldmatrix.
// ===========================================================================
#define BK      32
#define LDS_BF  40                       // bf16 elems per smem row (32 + 8 pad)
#define TILE_B  (128 * LDS_BF * 2)       // 10240 bytes per tile

__global__ void __launch_bounds__(256, 2) mma_gemm_bias(
    const float* __restrict__ A, const float* __restrict__ W,
    const float* __restrict__ bias, float* __restrict__ Cout,
    int ldb, int ldc)
{
    __shared__ __align__(16) __nv_bfloat16 sm[4 * 128 * LDS_BF];  // Ahi|Alo|Bhi|Blo

    __nv_bfloat16* Ahi = sm;
    __nv_bfloat16* Alo = sm + 128 * LDS_BF;
    __nv_bfloat16* Bhi = sm + 2 * 128 * LDS_BF;
    __nv_bfloat16* Blo = sm + 3 * 128 * LDS_BF;

    const uint32_t uAhi = smem_u32(Ahi);
    const uint32_t uAlo = smem_u32(Alo);
    const uint32_t uBhi = smem_u32(Bhi);
    const uint32_t uBlo = smem_u32(Blo);

    const int tid  = threadIdx.x;
    const int wid  = tid >> 5;
    const int lane = tid & 31;
    const int row0 = blockIdx.y * 128;
    const int col0 = blockIdx.x * 128;
    const int wm   = wid & 1;        // 2 warps in m
    const int wn   = wid >> 1;       // 4 warps in n

    float acc[4][4][4];              // [mi][ni][reg]
    #pragma unroll
    for (int i = 0; i < 4; i++)
        #pragma unroll
        for (int j = 0; j < 4; j++)
            #pragma unroll
            for (int r = 0; r < 4; r++) acc[i][j][r] = 0.0f;

    // ldmatrix lane addressing components
    const int a_row = lane & 15;            // row within 16-row A tile
    const int a_koff = (lane >> 4) << 3;    // 0 or 8
    const int b_rowsel = lane & 7;
    const int b_koff = ((lane >> 3) & 1) << 3;
    const int b_noff = (lane >> 4) << 3;

    for (int k0 = 0; k0 < 256; k0 += BK) {
        // ---- Load + convert A chunk: 128 rows x 32 k
        #pragma unroll
        for (int i = 0; i < 4; i++) {
            int e  = tid + i * 256;         // 0..1023 float4s
            int r  = e >> 3;                // 0..127
            int kk = (e & 7) << 2;          // 0..28
            float4 v = *reinterpret_cast<const float4*>(
                A + (size_t)(row0 + r) * 256 + k0 + kk);
            uint32_t h0, h1, l0, l1;
            split4(v, h0, h1, l0, l1);
            uint32_t off = (uint32_t)(r * LDS_BF + kk) * 2;   // bytes
            *reinterpret_cast<uint2*>((char*)Ahi + off) = make_uint2(h0, h1);
            *reinterpret_cast<uint2*>((char*)Alo + off) = make_uint2(l0, l1);
        }
        // ---- Load + convert B chunk transposed: Bs[n][kk] = W[k0+kk][col0+n]
        #pragma unroll
        for (int i = 0; i < 4; i++) {
            int e  = tid + i * 256;         // 0..1023 quads
            int n  = e & 127;
            int kk = (e >> 7) << 2;         // 0..28
            const float* wp = W + (size_t)(k0 + kk) * ldb + col0 + n;
            float4 v;
            v.x = wp[0];
            v.y = wp[(size_t)ldb];
            v.z = wp[(size_t)2 * ldb];
            v.w = wp[(size_t)3 * ldb];
            uint32_t h0, h1, l0, l1;
            split4(v, h0, h1, l0, l1);
            uint32_t off = (uint32_t)(n * LDS_BF + kk) * 2;
            *reinterpret_cast<uint2*>((char*)Bhi + off) = make_uint2(h0, h1);
            *reinterpret_cast<uint2*>((char*)Blo + off) = make_uint2(l0, l1);
        }
        __syncthreads();

        #pragma unroll
        for (int ks = 0; ks < 2; ks++) {
            const int kb = ks << 4;  // 0, 16

            // A fragments (hi), B fragments (hi + lo)
            uint32_t ah[4][4], bh[2][4], bl[2][4];
            #pragma unroll
            for (int mi = 0; mi < 4; mi++) {
                uint32_t addr = uAhi + (uint32_t)((wm * 64 + mi * 16 + a_row) * LDS_BF + kb + a_koff) * 2;
                ldm_x4(ah[mi], addr);
            }
            #pragma unroll
            for (int g = 0; g < 2; g++) {
                uint32_t roff = (uint32_t)((wn * 32 + g * 16 + b_noff + b_rowsel) * LDS_BF + kb + b_koff) * 2;
                ldm_x4(bh[g], uBhi + roff);
                ldm_x4(bl[g], uBlo + roff);
            }
            // term 1: Ahi * Bhi ; term 2: Ahi * Blo
            #pragma unroll
            for (int mi = 0; mi < 4; mi++)
                #pragma unroll
                for (int ni = 0; ni < 4; ni++) {
                    const uint32_t* bb = bh[ni >> 1];
                    mma16816(acc[mi][ni], ah[mi], bb[(ni & 1) * 2], bb[(ni & 1) * 2 + 1]);
                }
            #pragma unroll
            for (int mi = 0; mi < 4; mi++)
                #pragma unroll
                for (int ni = 0; ni < 4; ni++) {
                    const uint32_t* bb = bl[ni >> 1];
                    mma16816(acc[mi][ni], ah[mi], bb[(ni & 1) * 2], bb[(ni & 1) * 2 + 1]);
                }
            // term 3: Alo * Bhi  (reuse ah registers for alo)
            #pragma unroll
            for (int mi = 0; mi < 4; mi++) {
                uint32_t addr = uAlo + (uint32_t)((wm * 64 + mi * 16 + a_row) * LDS_BF + kb + a_koff) * 2;
                ldm_x4(ah[mi], addr);
            }
            #pragma unroll
            for (int mi = 0; mi < 4; mi++)
                #pragma unroll
                for (int ni = 0; ni < 4; ni++) {
                    const uint32_t* bb = bh[ni >> 1];
                    mma16816(acc[mi][ni], ah[mi], bb[(ni & 1) * 2], bb[(ni & 1) * 2 + 1]);
                }
        }
        __syncthreads();
    }

    // Epilogue: acc layout m16n8: c0,c1 at row grp, cols 2*(lane&3); c2,c3 at row grp+8
    const int grp  = lane >> 2;
    const int cpair = (lane & 3) << 1;
    #pragma unroll
    for (int mi = 0; mi < 4; mi++) {
        #pragma unroll
        for (int ni = 0; ni < 4; ni++) {
            int colg = col0 + wn * 32 + ni * 8 + cpair;
            float b0 = bias[colg], b1 = bias[colg + 1];
            int rowg = row0 + wm * 64 + mi * 16 + grp;
            float2 o0 = make_float2(acc[mi][ni][0] + b0, acc[mi][ni][1] + b1);
            float2 o1 = make_float2(acc[mi][ni][2] + b0, acc[mi][ni][3] + b1);
            *reinterpret_cast<float2*>(Cout + (size_t)rowg * ldc + colg) = o0;
            *reinterpret_cast<float2*>(Cout + (size_t)(rowg + 8) * ldc + colg) = o1;
        }
    }
}

// ---------------------------------------------------------------------------
// Softmax over L*P=16 per (query, head) + sampling locations
// ---------------------------------------------------------------------------
__global__ __launch_bounds__(128) void softmax_loc_kernel(
    const float* __restrict__ refp,
    float* __restrict__ out_loc,
    float* __restrict__ out_attn)
{
    const int q = blockIdx.x;
    const int t = threadIdx.x;
    const int m = t >> 4;
    const int l = (t >> 2) & 3;

    __shared__ float sh[128];
    const float* row = g_offattn + (size_t)q * 256;

    float off  = row[t];
    float araw = row[128 + t];

    sh[t] = araw;
    __syncthreads();
    float mx = -1e30f;
    #pragma unroll
    for (int i = 0; i < 16; i++) mx = fmaxf(mx, sh[(m << 4) + i]);
    float e = __expf(araw - mx);
    __syncthreads();
    sh[t] = e;
    __syncthreads();
    float s = 0.0f;
    #pragma unroll
    for (int i = 0; i < 16; i++) s += sh[(m << 4) + i];

    float attn = e / s;
    float loc  = refp[(size_t)q * 4 + l] + off * c_invT[l];

    out_loc [(size_t)q * 128 + t] = loc;
    out_attn[(size_t)q * 128 + t] = attn;
}

// ---------------------------------------------------------------------------
// Deformable sampling core
// ---------------------------------------------------------------------------
__global__ __launch_bounds__(256) void deform_kernel(
    const float* __restrict__ loc,
    const float* __restrict__ attn)
{
    const int q = blockIdx.x;
    const int n = q >> 11;
    const int t = threadIdx.x;
    const int m = t >> 5;
    const int d = t & 31;

    __shared__ float sLoc[128], sAttn[128];
    if (t < 128) {
        sLoc[t]  = loc [(size_t)q * 128 + t];
        sAttn[t] = attn[(size_t)q * 128 + t];
    }
    __syncthreads();

    const float* vbase = g_value + (size_t)n * S * C + m * DH + d;
    float acc = 0.0f;

    #pragma unroll
    for (int lp = 0; lp < 16; lp++) {
        const int l  = lp >> 2;
        const int Ti = c_tlen[l];
        const int st = c_tstart[l];

        float lv  = sLoc [(m << 4) + lp];
        float a   = sAttn[(m << 4) + lp];

        float pos  = lv * (float)Ti - 0.5f;
        float x0f  = floorf(pos);
        float frac = pos - x0f;
        int   x0   = (int)x0f;

        float w0 = (x0 >= 0 && x0 < Ti)         ? (1.0f - frac) : 0.0f;
        float w1 = (x0 + 1 >= 0 && x0 + 1 < Ti) ? frac          : 0.0f;

        int i0 = min(max(x0, 0), Ti - 1);
        int i1 = min(max(x0 + 1, 0), Ti - 1);

        float v0 = vbase[(size_t)(st + i0) * C];
        float v1 = vbase[(size_t)(st + i1) * C];
        acc = fmaf(a, fmaf(w0, v0, w1 * v1), acc);
    }

    g_deform[(size_t)q * C + t] = acc;
}

// ---------------------------------------------------------------------------
extern "C" void kernel_launch(void* const* d_in, const int* in_sizes, int n_in,
                              void* d_out, int out_size)
{
    const float* query  = (const float*)d_in[0];
    const float* refp   = (const float*)d_in[1];
    const float* inpf   = (const float*)d_in[2];
    const float* W_off  = (const float*)d_in[5];
    const float* b_off  = (const float*)d_in[6];
    const float* W_attn = (const float*)d_in[7];
    const float* b_attn = (const float*)d_in[8];
    const float* W_val  = (const float*)d_in[9];
    const float* b_val  = (const float*)d_in[10];
    const float* W_out  = (const float*)d_in[11];
    const float* b_out  = (const float*)d_in[12];

    float* out      = (float*)d_out;
    float* out_loc  = out + (size_t)NQ * C;
    float* out_attn = out_loc + (size_t)NQ * MLP;

    float *pValue, *pOffattn, *pDeform;
    cudaGetSymbolAddress((void**)&pValue,   g_value);
    cudaGetSymbolAddress((void**)&pOffattn, g_offattn);
    cudaGetSymbolAddress((void**)&pDeform,  g_deform);

    // 1) value = input_flatten @ W_val + b_val   (30720 x 256 x 256)
    mma_gemm_bias<<<dim3(2, 240), 256>>>(inpf, W_val, b_val, pValue, 256, 256);

    // 2) off raw = query @ W_off + b_off         (16384 x 256 x 128)
    mma_gemm_bias<<<dim3(1, 128), 256>>>(query, W_off, b_off, pOffattn, 128, 256);

    // 3) attn raw = query @ W_attn + b_attn
    mma_gemm_bias<<<dim3(1, 128), 256>>>(query, W_attn, b_attn, pOffattn + 128, 128, 256);

    // 4) softmax + sampling locations
    softmax_loc_kernel<<<NQ, 128>>>(refp, out_loc, out_attn);

    // 5) deformable gather
    deform_kernel<<<NQ, 256>>>(out_loc, out_attn);

    // 6) out = g_deform @ W_out + b_out          (16384 x 256 x 256)
    mma_gemm_bias<<<dim3(2, 128), 256>>>(pDeform, W_out, b_out, out, 256, 256);
}

// round 6
// speedup vs baseline: 1.9257x; 1.1669x over previous
#include <cuda_runtime.h>
#include <cuda_bf16.h>
#include <cstdint>

// Problem constants (static per reference)
#define NB   8
#define LQ   2048
#define C    256
#define M    8
#define L    4
#define P    4
#define DH   32
#define S    3840
#define NQ   (NB * LQ)          // 16384
#define MLP  (M * L * P)        // 128

__device__ __constant__ int   c_tlen[4]   = {2048, 1024, 512, 256};
__device__ __constant__ int   c_tstart[4] = {0, 2048, 3072, 3584};
__device__ __constant__ float c_invT[4]   = {1.0f/2048.0f, 1.0f/1024.0f, 1.0f/512.0f, 1.0f/256.0f};

// Scratch (device globals — no allocation allowed)
__device__ float g_value[NB * S * C];
__device__ float g_offattn[NQ * 256];     // [0:128)=off raw, [128:256)=attn raw
__device__ float g_deform[NQ * C];

// Pre-converted weights: transposed (n, k=256) bf16; rows [0,256)=hi, [256,512)=lo
__device__ __nv_bfloat16 g_wv[2 * 256 * 256];   // W_val^T
__device__ __nv_bfloat16 g_wq[2 * 256 * 256];   // [W_off | W_attn]^T
__device__ __nv_bfloat16 g_wo[2 * 256 * 256];   // W_out^T
__device__ float         g_bq[256];             // concat(b_off, b_attn)

// ===========================================================================
// Helpers
// ===========================================================================
__device__ __forceinline__ uint32_t smem_u32(const void* p) {
    uint32_t a;
    asm("{ .reg .u64 t; cvta.to.shared.u64 t, %1; cvt.u32.u64 %0, t; }" : "=r"(a) : "l"(p));
    return a;
}

__device__ __forceinline__ void ldm_x4(uint32_t* r, uint32_t addr) {
    asm volatile("ldmatrix.sync.aligned.m8n8.x4.shared.b16 {%0,%1,%2,%3}, [%4];"
                 : "=r"(r[0]), "=r"(r[1]), "=r"(r[2]), "=r"(r[3]) : "r"(addr));
}

__device__ __forceinline__ void mma16816(float* c, const uint32_t* a, uint32_t b0, uint32_t b1) {
    asm volatile("mma.sync.aligned.m16n8k16.row.col.f32.bf16.bf16.f32 "
                 "{%0,%1,%2,%3}, {%4,%5,%6,%7}, {%8,%9}, {%0,%1,%2,%3};"
                 : "+f"(c[0]), "+f"(c[1]), "+f"(c[2]), "+f"(c[3])
                 : "r"(a[0]), "r"(a[1]), "r"(a[2]), "r"(a[3]), "r"(b0), "r"(b1));
}

#define CP_ASYNC16(dst, src) \
    asm volatile("cp.async.cg.shared.global [%0], [%1], 16;" :: "r"(dst), "l"(src))
#define CP_COMMIT() asm volatile("cp.async.commit_group;" ::: "memory")
#define CP_WAIT1()  asm volatile("cp.async.wait_group 1;" ::: "memory")
#define CP_WAIT0()  asm volatile("cp.async.wait_group 0;" ::: "memory")

// Split fp32 -> bf16 hi + bf16 lo (packed pairs)
__device__ __forceinline__ void split4(float4 v, uint32_t& h0, uint32_t& h1,
                                       uint32_t& l0, uint32_t& l1) {
    __nv_bfloat16 a = __float2bfloat16_rn(v.x);
    __nv_bfloat16 b = __float2bfloat16_rn(v.y);
    __nv_bfloat16 c = __float2bfloat16_rn(v.z);
    __nv_bfloat16 d = __float2bfloat16_rn(v.w);
    __nv_bfloat162 H0 = __halves2bfloat162(a, b);
    __nv_bfloat162 H1 = __halves2bfloat162(c, d);
    __nv_bfloat162 L0 = __floats2bfloat162_rn(v.x - __bfloat162float(a), v.y - __bfloat162float(b));
    __nv_bfloat162 L1 = __floats2bfloat162_rn(v.z - __bfloat162float(c), v.w - __bfloat162float(d));
    h0 = *reinterpret_cast<uint32_t*>(&H0);
    h1 = *reinterpret_cast<uint32_t*>(&H1);
    l0 = *reinterpret_cast<uint32_t*>(&L0);
    l1 = *reinterpret_cast<uint32_t*>(&L1);
}

// ===========================================================================
// Weight pre-conversion: W (k-major fp32) -> W^T (n, 256) bf16 hi/lo.
// mat 0: W_val, mat 1: [W_off | W_attn], mat 2: W_out. grid 768 x 256.
// ===========================================================================
__global__ __launch_bounds__(256) void convert_weights(
    const float* __restrict__ Wv, const float* __restrict__ Woff,
    const float* __restrict__ Wattn, const float* __restrict__ Wo,
    const float* __restrict__ boff, const float* __restrict__ battn)
{
    int idx = blockIdx.x * 256 + threadIdx.x;   // 0 .. 3*65536
    int mat = idx >> 16;
    int r   = idx & 65535;
    int n   = r >> 8;
    int k   = r & 255;

    float v;
    if (mat == 0)      v = Wv[k * 256 + n];
    else if (mat == 1) v = (n < 128) ? Woff[k * 128 + n] : Wattn[k * 128 + (n - 128)];
    else               v = Wo[k * 256 + n];

    __nv_bfloat16 h = __float2bfloat16_rn(v);
    __nv_bfloat16 l = __float2bfloat16_rn(v - __bfloat162float(h));

    __nv_bfloat16* base = (mat == 0) ? g_wv : (mat == 1) ? g_wq : g_wo;
    base[n * 256 + k]         = h;
    base[65536 + n * 256 + k] = l;

    if (mat == 1 && k == 0)
        g_bq[n] = (n < 128) ? boff[n] : battn[n - 128];
}

// ===========================================================================
// Pipelined bf16-split tensor-core GEMM.
// C[r,c] = sum_k A[r,k]*W[k,c] + bias[c]. A row-major fp32 (K=256).
// Wt: pre-converted (n,256) bf16, hi at [0,65536), lo at [65536,131072).
// Block tile 128x128, BK=32, 8 warps (2m x 4n), warp tile 64x32.
// A: register prefetch 1 chunk ahead, split inline. B: cp.async double buffer.
// 3 MMA terms: Ahi*Bhi + Ahi*Blo + Alo*Bhi.
// ===========================================================================
#define LDS_BF 40                       // bf16/row (32 + 8 pad), 80 B
#define SM_A_HI 0
#define SM_A_LO 10240
#define SM_B(s) (20480 + (s) * 20480)   // each stage: hi @0, lo @10240
#define GEMM_SMEM 61440

__global__ void __launch_bounds__(256, 2) mma_gemm_bias(
    const float* __restrict__ A, const __nv_bfloat16* __restrict__ Wt,
    const float* __restrict__ bias, float* __restrict__ Cout)
{
    extern __shared__ __align__(128) char smem[];
    const uint32_t sb = smem_u32(smem);

    const int tid  = threadIdx.x;
    const int wid  = tid >> 5;
    const int lane = tid & 31;
    const int row0 = blockIdx.y * 128;
    const int col0 = blockIdx.x * 128;
    const int wm   = wid & 1;
    const int wn   = wid >> 1;

    float acc[4][4][4];
    #pragma unroll
    for (int i = 0; i < 4; i++)
        #pragma unroll
        for (int j = 0; j < 4; j++)
            #pragma unroll
            for (int r = 0; r < 4; r++) acc[i][j][r] = 0.0f;

    // ldmatrix lane addressing
    const int a_row    = lane & 15;
    const int a_koff   = (lane >> 4) << 3;
    const int b_rowsel = lane & 7;
    const int b_koff   = ((lane >> 3) & 1) << 3;
    const int b_noff   = (lane >> 4) << 3;

    // B cp.async issue for chunk with k offset k0 into stage st
    auto issueB = [&](int k0, int st) {
        #pragma unroll
        for (int i = 0; i < 4; i++) {
            int e   = tid + (i << 8);          // 0..1023
            int buf = e >> 9;                  // 0 hi, 1 lo
            int r   = (e >> 2) & 127;
            int q16 = e & 3;
            const __nv_bfloat16* src =
                Wt + (size_t)buf * 65536 + (size_t)(col0 + r) * 256 + k0 + (q16 << 3);
            uint32_t dst = sb + SM_B(st) + buf * 10240 + r * 80 + (q16 << 4);
            CP_ASYNC16(dst, src);
        }
    };

    // Prologue: A chunk 0 -> regs, B chunk 0 -> stage 0
    float4 aReg[4];
    #pragma unroll
    for (int i = 0; i < 4; i++) {
        int e = tid + (i << 8);
        int r = e >> 3;
        int kk = (e & 7) << 2;
        aReg[i] = *reinterpret_cast<const float4*>(A + (size_t)(row0 + r) * 256 + kk);
    }
    issueB(0, 0);
    CP_COMMIT();

    for (int c = 0; c < 8; c++) {
        if (c) __syncthreads();            // MMA(c-1) done -> A smem + stage (c+1)&1 free

        // Split + store A chunk c
        #pragma unroll
        for (int i = 0; i < 4; i++) {
            int e = tid + (i << 8);
            int r = e >> 3;
            int kk = (e & 7) << 2;
            uint32_t h0, h1, l0, l1;
            split4(aReg[i], h0, h1, l0, l1);
            uint32_t off = (uint32_t)(r * LDS_BF + kk) * 2;
            *reinterpret_cast<uint2*>(smem + SM_A_HI + off) = make_uint2(h0, h1);
            *reinterpret_cast<uint2*>(smem + SM_A_LO + off) = make_uint2(l0, l1);
        }

        if (c < 7) {
            const int k0n = (c + 1) << 5;
            #pragma unroll
            for (int i = 0; i < 4; i++) {
                int e = tid + (i << 8);
                int r = e >> 3;
                int kk = (e & 7) << 2;
                aReg[i] = *reinterpret_cast<const float4*>(
                    A + (size_t)(row0 + r) * 256 + k0n + kk);
            }
            issueB(k0n, (c + 1) & 1);
            CP_COMMIT();
            CP_WAIT1();                    // chunk c's B group done
        } else {
            CP_WAIT0();
        }
        __syncthreads();

        // MMA on chunk c
        const uint32_t uAhi = sb + SM_A_HI;
        const uint32_t uAlo = sb + SM_A_LO;
        const uint32_t uBhi = sb + SM_B(c & 1);
        const uint32_t uBlo = uBhi + 10240;

        #pragma unroll
        for (int ks = 0; ks < 2; ks++) {
            const int kb = ks << 4;

            uint32_t ah[4][4], bh[2][4], bl[2][4];
            #pragma unroll
            for (int mi = 0; mi < 4; mi++) {
                uint32_t addr = uAhi + (uint32_t)((wm * 64 + mi * 16 + a_row) * LDS_BF + kb + a_koff) * 2;
                ldm_x4(ah[mi], addr);
            }
            #pragma unroll
            for (int g = 0; g < 2; g++) {
                uint32_t roff = (uint32_t)((wn * 32 + g * 16 + b_noff + b_rowsel) * LDS_BF + kb + b_koff) * 2;
                ldm_x4(bh[g], uBhi + roff);
                ldm_x4(bl[g], uBlo + roff);
            }
            #pragma unroll
            for (int mi = 0; mi < 4; mi++)
                #pragma unroll
                for (int ni = 0; ni < 4; ni++) {
                    const uint32_t* bb = bh[ni >> 1];
                    mma16816(acc[mi][ni], ah[mi], bb[(ni & 1) * 2], bb[(ni & 1) * 2 + 1]);
                }
            #pragma unroll
            for (int mi = 0; mi < 4; mi++)
                #pragma unroll
                for (int ni = 0; ni < 4; ni++) {
                    const uint32_t* bb = bl[ni >> 1];
                    mma16816(acc[mi][ni], ah[mi], bb[(ni & 1) * 2], bb[(ni & 1) * 2 + 1]);
                }
            #pragma unroll
            for (int mi = 0; mi < 4; mi++) {
                uint32_t addr = uAlo + (uint32_t)((wm * 64 + mi * 16 + a_row) * LDS_BF + kb + a_koff) * 2;
                ldm_x4(ah[mi], addr);
            }
            #pragma unroll
            for (int mi = 0; mi < 4; mi++)
                #pragma unroll
                for (int ni = 0; ni < 4; ni++) {
                    const uint32_t* bb = bh[ni >> 1];
                    mma16816(acc[mi][ni], ah[mi], bb[(ni & 1) * 2], bb[(ni & 1) * 2 + 1]);
                }
        }
    }

    // Epilogue
    const int grp   = lane >> 2;
    const int cpair = (lane & 3) << 1;
    #pragma unroll
    for (int mi = 0; mi < 4; mi++) {
        #pragma unroll
        for (int ni = 0; ni < 4; ni++) {
            int colg = col0 + wn * 32 + ni * 8 + cpair;
            float b0 = bias[colg], b1 = bias[colg + 1];
            int rowg = row0 + wm * 64 + mi * 16 + grp;
            float2 o0 = make_float2(acc[mi][ni][0] + b0, acc[mi][ni][1] + b1);
            float2 o1 = make_float2(acc[mi][ni][2] + b0, acc[mi][ni][3] + b1);
            *reinterpret_cast<float2*>(Cout + (size_t)rowg * 256 + colg) = o0;
            *reinterpret_cast<float2*>(Cout + (size_t)(rowg + 8) * 256 + colg) = o1;
        }
    }
}

// ---------------------------------------------------------------------------
// Fused softmax + loc + deformable gather. One block (256 thr) per query.
// Threads <128 compute loc/attn (shfl reduction over 16-lane groups), write
// them to the output AND smem; then all 256 threads gather (warp=head).
// ---------------------------------------------------------------------------
__global__ __launch_bounds__(256) void deform_fused(
    const float* __restrict__ refp,
    float* __restrict__ out_loc,
    float* __restrict__ out_attn)
{
    const int q = blockIdx.x;
    const int n = q >> 11;
    const int t = threadIdx.x;

    __shared__ float sLoc[128], sAttn[128];

    if (t < 128) {
        const int l = (t >> 2) & 3;
        const float* row = g_offattn + (size_t)q * 256;
        float off  = row[t];
        float araw = row[128 + t];

        float mx = araw;
        #pragma unroll
        for (int d = 1; d < 16; d <<= 1)
            mx = fmaxf(mx, __shfl_xor_sync(0xffffffffu, mx, d));
        float e = __expf(araw - mx);
        float s = e;
        #pragma unroll
        for (int d = 1; d < 16; d <<= 1)
            s += __shfl_xor_sync(0xffffffffu, s, d);

        float attn = e / s;
        float loc  = refp[(size_t)q * 4 + l] + off * c_invT[l];

        sLoc[t]  = loc;
        sAttn[t] = attn;
        out_loc [(size_t)q * 128 + t] = loc;
        out_attn[(size_t)q * 128 + t] = attn;
    }
    __syncthreads();

    const int m = t >> 5;
    const int d = t & 31;
    const float* vbase = g_value + (size_t)n * S * C + m * DH + d;
    float acc = 0.0f;

    #pragma unroll
    for (int lp = 0; lp < 16; lp++) {
        const int l  = lp >> 2;
        const int Ti = c_tlen[l];
        const int st = c_tstart[l];

        float lv = sLoc [(m << 4) + lp];
        float a  = sAttn[(m << 4) + lp];

        float pos  = lv * (float)Ti - 0.5f;
        float x0f  = floorf(pos);
        float frac = pos - x0f;
        int   x0   = (int)x0f;

        float w0 = (x0 >= 0 && x0 < Ti)         ? (1.0f - frac) : 0.0f;
        float w1 = (x0 + 1 >= 0 && x0 + 1 < Ti) ? frac          : 0.0f;

        int i0 = min(max(x0, 0), Ti - 1);
        int i1 = min(max(x0 + 1, 0), Ti - 1);

        float v0 = vbase[(size_t)(st + i0) * C];
        float v1 = vbase[(size_t)(st + i1) * C];
        acc = fmaf(a, fmaf(w0, v0, w1 * v1), acc);
    }

    g_deform[(size_t)q * C + t] = acc;
}

// ---------------------------------------------------------------------------
extern "C" void kernel_launch(void* const* d_in, const int* in_sizes, int n_in,
                              void* d_out, int out_size)
{
    const float* query  = (const float*)d_in[0];
    const float* refp   = (const float*)d_in[1];
    const float* inpf   = (const float*)d_in[2];
    const float* W_off  = (const float*)d_in[5];
    const float* b_off  = (const float*)d_in[6];
    const float* W_attn = (const float*)d_in[7];
    const float* b_attn = (const float*)d_in[8];
    const float* W_val  = (const float*)d_in[9];
    const float* b_val  = (const float*)d_in[10];
    const float* W_out  = (const float*)d_in[11];
    const float* b_out  = (const float*)d_in[12];

    float* out      = (float*)d_out;
    float* out_loc  = out + (size_t)NQ * C;
    float* out_attn = out_loc + (size_t)NQ * MLP;

    float *pValue, *pOffattn, *pDeform, *pBq;
    __nv_bfloat16 *pWv, *pWq, *pWo;
    cudaGetSymbolAddress((void**)&pValue,   g_value);
    cudaGetSymbolAddress((void**)&pOffattn, g_offattn);
    cudaGetSymbolAddress((void**)&pDeform,  g_deform);
    cudaGetSymbolAddress((void**)&pWv,      g_wv);
    cudaGetSymbolAddress((void**)&pWq,      g_wq);
    cudaGetSymbolAddress((void**)&pWo,      g_wo);
    cudaGetSymbolAddress((void**)&pBq,      g_bq);

    cudaFuncSetAttribute(mma_gemm_bias, cudaFuncAttributeMaxDynamicSharedMemorySize, GEMM_SMEM);

    // 0) pre-convert weights to transposed bf16 hi/lo
    convert_weights<<<768, 256>>>(W_val, W_off, W_attn, W_out, b_off, b_attn);

    // 1) value = input_flatten @ W_val + b_val   (30720 x 256 x 256)
    mma_gemm_bias<<<dim3(2, 240), 256, GEMM_SMEM>>>(inpf, pWv, b_val, pValue);

    // 2) [off | attn] raw = query @ [W_off|W_attn] + [b]   (16384 x 256 x 256)
    mma_gemm_bias<<<dim3(2, 128), 256, GEMM_SMEM>>>(query, pWq, pBq, pOffattn);

    // 3) fused softmax + loc + deformable gather
    deform_fused<<<NQ, 256>>>(refp, out_loc, out_attn);

    // 4) out = g_deform @ W_out + b_out          (16384 x 256 x 256)
    mma_gemm_bias<<<dim3(2, 128), 256, GEMM_SMEM>>>(pDeform, pWo, b_out, out);
}

// round 8
// speedup vs baseline: 2.3495x; 1.2201x over previous
#include <cuda_runtime.h>
#include <cuda_bf16.h>
#include <cstdint>

// Problem constants (static per reference)
#define NB   8
#define LQ   2048
#define C    256
#define M    8
#define L    4
#define P    4
#define DH   32
#define S    3840
#define NQ   (NB * LQ)          // 16384
#define MLP  (M * L * P)        // 128

__device__ __constant__ int   c_tlen[4]   = {2048, 1024, 512, 256};
__device__ __constant__ int   c_tstart[4] = {0, 2048, 3072, 3584};
__device__ __constant__ float c_invT[4]   = {1.0f/2048.0f, 1.0f/1024.0f, 1.0f/512.0f, 1.0f/256.0f};

// Scratch (device globals — no allocation allowed)
__device__ float g_value[NB * S * C];
__device__ float g_offattn[NQ * 256];     // [0:128)=off raw, [128:256)=attn raw
__device__ float g_deform[NQ * C];

// Pre-converted weights: transposed (n, k=256) bf16; hi at [0,65536), lo after
__device__ __nv_bfloat16 g_wv[2 * 256 * 256];   // W_val^T
__device__ __nv_bfloat16 g_wq[2 * 256 * 256];   // [W_off | W_attn]^T
__device__ __nv_bfloat16 g_wo[2 * 256 * 256];   // W_out^T
__device__ float         g_bq[256];             // concat(b_off, b_attn)

// ===========================================================================
// Helpers
// ===========================================================================
__device__ __forceinline__ uint32_t smem_u32(const void* p) {
    uint32_t a;
    asm("{ .reg .u64 t; cvta.to.shared.u64 t, %1; cvt.u32.u64 %0, t; }" : "=r"(a) : "l"(p));
    return a;
}

__device__ __forceinline__ void ldm_x4(uint32_t* r, uint32_t addr) {
    asm volatile("ldmatrix.sync.aligned.m8n8.x4.shared.b16 {%0,%1,%2,%3}, [%4];"
                 : "=r"(r[0]), "=r"(r[1]), "=r"(r[2]), "=r"(r[3]) : "r"(addr));
}

__device__ __forceinline__ void mma16816(float* c, const uint32_t* a, uint32_t b0, uint32_t b1) {
    asm volatile("mma.sync.aligned.m16n8k16.row.col.f32.bf16.bf16.f32 "
                 "{%0,%1,%2,%3}, {%4,%5,%6,%7}, {%8,%9}, {%0,%1,%2,%3};"
                 : "+f"(c[0]), "+f"(c[1]), "+f"(c[2]), "+f"(c[3])
                 : "r"(a[0]), "r"(a[1]), "r"(a[2]), "r"(a[3]), "r"(b0), "r"(b1));
}

#define CP_ASYNC16(dst, src) \
    asm volatile("cp.async.cg.shared.global [%0], [%1], 16;" :: "r"(dst), "l"(src))
#define CP_COMMIT() asm volatile("cp.async.commit_group;" ::: "memory")
#define CP_WAIT1()  asm volatile("cp.async.wait_group 1;" ::: "memory")
#define CP_WAIT0()  asm volatile("cp.async.wait_group 0;" ::: "memory")

// Split fp32 -> bf16 hi + bf16 lo (packed pairs)
__device__ __forceinline__ void split4(float4 v, uint32_t& h0, uint32_t& h1,
                                       uint32_t& l0, uint32_t& l1) {
    __nv_bfloat16 a = __float2bfloat16_rn(v.x);
    __nv_bfloat16 b = __float2bfloat16_rn(v.y);
    __nv_bfloat16 c = __float2bfloat16_rn(v.z);
    __nv_bfloat16 d = __float2bfloat16_rn(v.w);
    __nv_bfloat162 H0 = __halves2bfloat162(a, b);
    __nv_bfloat162 H1 = __halves2bfloat162(c, d);
    __nv_bfloat162 L0 = __floats2bfloat162_rn(v.x - __bfloat162float(a), v.y - __bfloat162float(b));
    __nv_bfloat162 L1 = __floats2bfloat162_rn(v.z - __bfloat162float(c), v.w - __bfloat162float(d));
    h0 = *reinterpret_cast<uint32_t*>(&H0);
    h1 = *reinterpret_cast<uint32_t*>(&H1);
    l0 = *reinterpret_cast<uint32_t*>(&L0);
    l1 = *reinterpret_cast<uint32_t*>(&L1);
}

// ===========================================================================
// Weight pre-conversion
// ===========================================================================
__global__ __launch_bounds__(256) void convert_weights(
    const float* __restrict__ Wv, const float* __restrict__ Woff,
    const float* __restrict__ Wattn, const float* __restrict__ Wo,
    const float* __restrict__ boff, const float* __restrict__ battn)
{
    int idx = blockIdx.x * 256 + threadIdx.x;
    int mat = idx >> 16;
    int r   = idx & 65535;
    int n   = r >> 8;
    int k   = r & 255;

    float v;
    if (mat == 0)      v = Wv[k * 256 + n];
    else if (mat == 1) v = (n < 128) ? Woff[k * 128 + n] : Wattn[k * 128 + (n - 128)];
    else               v = Wo[k * 256 + n];

    __nv_bfloat16 h = __float2bfloat16_rn(v);
    __nv_bfloat16 l = __float2bfloat16_rn(v - __bfloat162float(h));

    __nv_bfloat16* base = (mat == 0) ? g_wv : (mat == 1) ? g_wq : g_wo;
    base[n * 256 + k]         = h;
    base[65536 + n * 256 + k] = l;

    if (mat == 1 && k == 0)
        g_bq[n] = (n < 128) ? boff[n] : battn[n - 128];
}

// ===========================================================================
// Pipelined bf16-split tensor-core GEMM (dual problem set in one launch).
// Blocks with by < nby1 run problem 1, the rest problem 2.
// ===========================================================================
#define LDS_BF 40
#define SM_A_HI 0
#define SM_A_LO 10240
#define SM_B(s) (20480 + (s) * 20480)
#define GEMM_SMEM 61440

__global__ void __launch_bounds__(256, 2) mma_gemm_bias2(
    const float* __restrict__ A1, const __nv_bfloat16* __restrict__ Wt1,
    const float* __restrict__ bias1, float* __restrict__ C1, int nby1,
    const float* __restrict__ A2, const __nv_bfloat16* __restrict__ Wt2,
    const float* __restrict__ bias2, float* __restrict__ C2)
{
    extern __shared__ __align__(128) char smem[];
    const uint32_t sb = smem_u32(smem);

    const int by = blockIdx.y;
    const bool p1 = (by < nby1);
    const float*         A    = p1 ? A1    : A2;
    const __nv_bfloat16* Wt   = p1 ? Wt1   : Wt2;
    const float*         bias = p1 ? bias1 : bias2;
    float*               Cout = p1 ? C1    : C2;

    const int tid  = threadIdx.x;
    const int wid  = tid >> 5;
    const int lane = tid & 31;
    const int row0 = (p1 ? by : (by - nby1)) * 128;
    const int col0 = blockIdx.x * 128;
    const int wm   = wid & 1;
    const int wn   = wid >> 1;

    float acc[4][4][4];
    #pragma unroll
    for (int i = 0; i < 4; i++)
        #pragma unroll
        for (int j = 0; j < 4; j++)
            #pragma unroll
            for (int r = 0; r < 4; r++) acc[i][j][r] = 0.0f;

    const int a_row    = lane & 15;
    const int a_koff   = (lane >> 4) << 3;
    const int b_rowsel = lane & 7;
    const int b_koff   = ((lane >> 3) & 1) << 3;
    const int b_noff   = (lane >> 4) << 3;

    auto issueB = [&](int k0, int st) {
        #pragma unroll
        for (int i = 0; i < 4; i++) {
            int e   = tid + (i << 8);
            int buf = e >> 9;
            int r   = (e >> 2) & 127;
            int q16 = e & 3;
            const __nv_bfloat16* src =
                Wt + (size_t)buf * 65536 + (size_t)(col0 + r) * 256 + k0 + (q16 << 3);
            uint32_t dst = sb + SM_B(st) + buf * 10240 + r * 80 + (q16 << 4);
            CP_ASYNC16(dst, src);
        }
    };

    float4 aReg[4];
    #pragma unroll
    for (int i = 0; i < 4; i++) {
        int e = tid + (i << 8);
        int r = e >> 3;
        int kk = (e & 7) << 2;
        aReg[i] = *reinterpret_cast<const float4*>(A + (size_t)(row0 + r) * 256 + kk);
    }
    issueB(0, 0);
    CP_COMMIT();

    for (int c = 0; c < 8; c++) {
        if (c) __syncthreads();

        #pragma unroll
        for (int i = 0; i < 4; i++) {
            int e = tid + (i << 8);
            int r = e >> 3;
            int kk = (e & 7) << 2;
            uint32_t h0, h1, l0, l1;
            split4(aReg[i], h0, h1, l0, l1);
            uint32_t off = (uint32_t)(r * LDS_BF + kk) * 2;
            *reinterpret_cast<uint2*>(smem + SM_A_HI + off) = make_uint2(h0, h1);
            *reinterpret_cast<uint2*>(smem + SM_A_LO + off) = make_uint2(l0, l1);
        }

        if (c < 7) {
            const int k0n = (c + 1) << 5;
            #pragma unroll
            for (int i = 0; i < 4; i++) {
                int e = tid + (i << 8);
                int r = e >> 3;
                int kk = (e & 7) << 2;
                aReg[i] = *reinterpret_cast<const float4*>(
                    A + (size_t)(row0 + r) * 256 + k0n + kk);
            }
            issueB(k0n, (c + 1) & 1);
            CP_COMMIT();
            CP_WAIT1();
        } else {
            CP_WAIT0();
        }
        __syncthreads();

        const uint32_t uAhi = sb + SM_A_HI;
        const uint32_t uAlo = sb + SM_A_LO;
        const uint32_t uBhi = sb + SM_B(c & 1);
        const uint32_t uBlo = uBhi + 10240;

        #pragma unroll
        for (int ks = 0; ks < 2; ks++) {
            const int kb = ks << 4;

            uint32_t ah[4][4], bh[2][4], bl[2][4];
            #pragma unroll
            for (int mi = 0; mi < 4; mi++) {
                uint32_t addr = uAhi + (uint32_t)((wm * 64 + mi * 16 + a_row) * LDS_BF + kb + a_koff) * 2;
                ldm_x4(ah[mi], addr);
            }
            #pragma unroll
            for (int g = 0; g < 2; g++) {
                uint32_t roff = (uint32_t)((wn * 32 + g * 16 + b_noff + b_rowsel) * LDS_BF + kb + b_koff) * 2;
                ldm_x4(bh[g], uBhi + roff);
                ldm_x4(bl[g], uBlo + roff);
            }
            #pragma unroll
            for (int mi = 0; mi < 4; mi++)
                #pragma unroll
                for (int ni = 0; ni < 4; ni++) {
                    const uint32_t* bb = bh[ni >> 1];
                    mma16816(acc[mi][ni], ah[mi], bb[(ni & 1) * 2], bb[(ni & 1) * 2 + 1]);
                }
            #pragma unroll
            for (int mi = 0; mi < 4; mi++)
                #pragma unroll
                for (int ni = 0; ni < 4; ni++) {
                    const uint32_t* bb = bl[ni >> 1];
                    mma16816(acc[mi][ni], ah[mi], bb[(ni & 1) * 2], bb[(ni & 1) * 2 + 1]);
                }
            #pragma unroll
            for (int mi = 0; mi < 4; mi++) {
                uint32_t addr = uAlo + (uint32_t)((wm * 64 + mi * 16 + a_row) * LDS_BF + kb + a_koff) * 2;
                ldm_x4(ah[mi], addr);
            }
            #pragma unroll
            for (int mi = 0; mi < 4; mi++)
                #pragma unroll
                for (int ni = 0; ni < 4; ni++) {
                    const uint32_t* bb = bh[ni >> 1];
                    mma16816(acc[mi][ni], ah[mi], bb[(ni & 1) * 2], bb[(ni & 1) * 2 + 1]);
                }
        }
    }

    const int grp   = lane >> 2;
    const int cpair = (lane & 3) << 1;
    #pragma unroll
    for (int mi = 0; mi < 4; mi++) {
        #pragma unroll
        for (int ni = 0; ni < 4; ni++) {
            int colg = col0 + wn * 32 + ni * 8 + cpair;
            float b0 = bias[colg], b1 = bias[colg + 1];
            int rowg = row0 + wm * 64 + mi * 16 + grp;
            float2 o0 = make_float2(acc[mi][ni][0] + b0, acc[mi][ni][1] + b1);
            float2 o1 = make_float2(acc[mi][ni][2] + b0, acc[mi][ni][3] + b1);
            *reinterpret_cast<float2*>(Cout + (size_t)rowg * 256 + colg) = o0;
            *reinterpret_cast<float2*>(Cout + (size_t)(rowg + 8) * 256 + colg) = o1;
        }
    }
}

// ---------------------------------------------------------------------------
// Fused softmax + loc + deformable gather. One block (256 thr) per query.
// Phase 1 (t<128, one per (head,point)): softmax, loc, AND all index/weight
// math — packed as int4 {w0*attn, w1*attn, byteoff0, byteoff1} in smem.
// Phase 2 (all 256, warp=head, lane=channel): pure LDS.128 + 2xLDG + 2xFFMA.
// ---------------------------------------------------------------------------
__global__ __launch_bounds__(256) void deform_fused(
    const float* __restrict__ refp,
    float* __restrict__ out_loc,
    float* __restrict__ out_attn)
{
    const int q = blockIdx.x;
    const int n = q >> 11;
    const int t = threadIdx.x;

    __shared__ int4 sPack[128];

    if (t < 128) {
        const int l = (t >> 2) & 3;
        const float* row = g_offattn + (size_t)q * 256;
        float off  = row[t];
        float araw = row[128 + t];

        float mx = araw;
        #pragma unroll
        for (int d = 1; d < 16; d <<= 1)
            mx = fmaxf(mx, __shfl_xor_sync(0xffffffffu, mx, d));
        float e = __expf(araw - mx);
        float s = e;
        #pragma unroll
        for (int d = 1; d < 16; d <<= 1)
            s += __shfl_xor_sync(0xffffffffu, s, d);

        float attn = e / s;
        float loc  = refp[(size_t)q * 4 + l] + off * c_invT[l];

        out_loc [(size_t)q * 128 + t] = loc;
        out_attn[(size_t)q * 128 + t] = attn;

        const int Ti = c_tlen[l];
        const int st = c_tstart[l];
        float pos  = loc * (float)Ti - 0.5f;
        float x0f  = floorf(pos);
        float frac = pos - x0f;
        int   x0   = (int)x0f;

        float w0 = (x0 >= 0 && x0 < Ti)         ? (1.0f - frac) * attn : 0.0f;
        float w1 = (x0 + 1 >= 0 && x0 + 1 < Ti) ? frac * attn          : 0.0f;

        int i0 = min(max(x0, 0), Ti - 1) + st;
        int i1 = min(max(x0 + 1, 0), Ti - 1) + st;

        sPack[t] = make_int4(__float_as_int(w0), __float_as_int(w1),
                             i0 << 10, i1 << 10);   // byte offsets (row = 1024 B)
    }
    __syncthreads();

    const int m = t >> 5;
    const int d = t & 31;
    const char* base = (const char*)(g_value + (size_t)n * S * C + m * DH + d);
    const int4* pk = &sPack[m << 4];

    float acc = 0.0f;
    #pragma unroll
    for (int lp = 0; lp < 16; lp++) {
        int4 p = pk[lp];
        float v0 = *reinterpret_cast<const float*>(base + p.z);
        float v1 = *reinterpret_cast<const float*>(base + p.w);
        acc = fmaf(__int_as_float(p.x), v0, acc);
        acc = fmaf(__int_as_float(p.y), v1, acc);
    }

    g_deform[(size_t)q * C + t] = acc;
}

// ---------------------------------------------------------------------------
extern "C" void kernel_launch(void* const* d_in, const int* in_sizes, int n_in,
                              void* d_out, int out_size)
{
    const float* query  = (const float*)d_in[0];
    const float* refp   = (const float*)d_in[1];
    const float* inpf   = (const float*)d_in[2];
    const float* W_off  = (const float*)d_in[5];
    const float* b_off  = (const float*)d_in[6];
    const float* W_attn = (const float*)d_in[7];
    const float* b_attn = (const float*)d_in[8];
    const float* W_val  = (const float*)d_in[9];
    const float* b_val  = (const float*)d_in[10];
    const float* W_out  = (const float*)d_in[11];
    const float* b_out  = (const float*)d_in[12];

    float* out      = (float*)d_out;
    float* out_loc  = out + (size_t)NQ * C;
    float* out_attn = out_loc + (size_t)NQ * MLP;

    float *pValue, *pOffattn, *pDeform, *pBq;
    __nv_bfloat16 *pWv, *pWq, *pWo;
    cudaGetSymbolAddress((void**)&pValue,   g_value);
    cudaGetSymbolAddress((void**)&pOffattn, g_offattn);
    cudaGetSymbolAddress((void**)&pDeform,  g_deform);
    cudaGetSymbolAddress((void**)&pWv,      g_wv);
    cudaGetSymbolAddress((void**)&pWq,      g_wq);
    cudaGetSymbolAddress((void**)&pWo,      g_wo);
    cudaGetSymbolAddress((void**)&pBq,      g_bq);

    cudaFuncSetAttribute(mma_gemm_bias2, cudaFuncAttributeMaxDynamicSharedMemorySize, GEMM_SMEM);

    // 0) pre-convert weights
    convert_weights<<<768, 256>>>(W_val, W_off, W_attn, W_out, b_off, b_attn);

    // 1+2) value GEMM (240 row-blocks) + off/attn GEMM (128 row-blocks), one launch
    mma_gemm_bias2<<<dim3(2, 368), 256, GEMM_SMEM>>>(
        inpf, pWv, b_val, pValue, 240,
        query, pWq, pBq, pOffattn);

    // 3) fused softmax + loc + deformable gather
    deform_fused<<<NQ, 256>>>(refp, out_loc, out_attn);

    // 4) out = g_deform @ W_out + b_out
    mma_gemm_bias2<<<dim3(2, 128), 256, GEMM_SMEM>>>(
        pDeform, pWo, b_out, out, 128,
        pDeform, pWo, b_out, out);
}

// round 9
// speedup vs baseline: 2.4506x; 1.0430x over previous
#include <cuda_runtime.h>
#include <cuda_bf16.h>
#include <cuda_fp16.h>
#include <cstdint>

// Problem constants (static per reference)
#define NB   8
#define LQ   2048
#define C    256
#define M    8
#define L    4
#define P    4
#define DH   32
#define S    3840
#define NQ   (NB * LQ)          // 16384
#define MLP  (M * L * P)        // 128

__device__ __constant__ int   c_tlen[4]   = {2048, 1024, 512, 256};
__device__ __constant__ int   c_tstart[4] = {0, 2048, 3072, 3584};
__device__ __constant__ float c_invT[4]   = {1.0f/2048.0f, 1.0f/1024.0f, 1.0f/512.0f, 1.0f/256.0f};

// Scratch (device globals — no allocation allowed)
__device__ __half g_value_h[NB * S * C];  // value in fp16 (consumed only by deform)
__device__ float g_offattn[NQ * 256];     // [0:128)=off raw, [128:256)=attn raw
__device__ float g_deform[NQ * C];

// Pre-converted weights: transposed (n, k=256) bf16; hi at [0,65536), lo after
__device__ __nv_bfloat16 g_wv[2 * 256 * 256];
__device__ __nv_bfloat16 g_wq[2 * 256 * 256];
__device__ __nv_bfloat16 g_wo[2 * 256 * 256];
__device__ float         g_bq[256];

// ===========================================================================
// Helpers
// ===========================================================================
__device__ __forceinline__ uint32_t smem_u32(const void* p) {
    uint32_t a;
    asm("{ .reg .u64 t; cvta.to.shared.u64 t, %1; cvt.u32.u64 %0, t; }" : "=r"(a) : "l"(p));
    return a;
}

__device__ __forceinline__ void ldm_x4(uint32_t* r, uint32_t addr) {
    asm volatile("ldmatrix.sync.aligned.m8n8.x4.shared.b16 {%0,%1,%2,%3}, [%4];"
                 : "=r"(r[0]), "=r"(r[1]), "=r"(r[2]), "=r"(r[3]) : "r"(addr));
}

__device__ __forceinline__ void mma16816(float* c, const uint32_t* a, uint32_t b0, uint32_t b1) {
    asm volatile("mma.sync.aligned.m16n8k16.row.col.f32.bf16.bf16.f32 "
                 "{%0,%1,%2,%3}, {%4,%5,%6,%7}, {%8,%9}, {%0,%1,%2,%3};"
                 : "+f"(c[0]), "+f"(c[1]), "+f"(c[2]), "+f"(c[3])
                 : "r"(a[0]), "r"(a[1]), "r"(a[2]), "r"(a[3]), "r"(b0), "r"(b1));
}

#define CP_ASYNC16(dst, src) \
    asm volatile("cp.async.cg.shared.global [%0], [%1], 16;" :: "r"(dst), "l"(src))
#define CP_COMMIT() asm volatile("cp.async.commit_group;" ::: "memory")
#define CP_WAIT1()  asm volatile("cp.async.wait_group 1;" ::: "memory")
#define CP_WAIT0()  asm volatile("cp.async.wait_group 0;" ::: "memory")

__device__ __forceinline__ void split4(float4 v, uint32_t& h0, uint32_t& h1,
                                       uint32_t& l0, uint32_t& l1) {
    __nv_bfloat16 a = __float2bfloat16_rn(v.x);
    __nv_bfloat16 b = __float2bfloat16_rn(v.y);
    __nv_bfloat16 c = __float2bfloat16_rn(v.z);
    __nv_bfloat16 d = __float2bfloat16_rn(v.w);
    __nv_bfloat162 H0 = __halves2bfloat162(a, b);
    __nv_bfloat162 H1 = __halves2bfloat162(c, d);
    __nv_bfloat162 L0 = __floats2bfloat162_rn(v.x - __bfloat162float(a), v.y - __bfloat162float(b));
    __nv_bfloat162 L1 = __floats2bfloat162_rn(v.z - __bfloat162float(c), v.w - __bfloat162float(d));
    h0 = *reinterpret_cast<uint32_t*>(&H0);
    h1 = *reinterpret_cast<uint32_t*>(&H1);
    l0 = *reinterpret_cast<uint32_t*>(&L0);
    l1 = *reinterpret_cast<uint32_t*>(&L1);
}

// ===========================================================================
// Weight pre-conversion
// ===========================================================================
__global__ __launch_bounds__(256) void convert_weights(
    const float* __restrict__ Wv, const float* __restrict__ Woff,
    const float* __restrict__ Wattn, const float* __restrict__ Wo,
    const float* __restrict__ boff, const float* __restrict__ battn)
{
    int idx = blockIdx.x * 256 + threadIdx.x;
    int mat = idx >> 16;
    int r   = idx & 65535;
    int n   = r >> 8;
    int k   = r & 255;

    float v;
    if (mat == 0)      v = Wv[k * 256 + n];
    else if (mat == 1) v = (n < 128) ? Woff[k * 128 + n] : Wattn[k * 128 + (n - 128)];
    else               v = Wo[k * 256 + n];

    __nv_bfloat16 h = __float2bfloat16_rn(v);
    __nv_bfloat16 l = __float2bfloat16_rn(v - __bfloat162float(h));

    __nv_bfloat16* base = (mat == 0) ? g_wv : (mat == 1) ? g_wq : g_wo;
    base[n * 256 + k]         = h;
    base[65536 + n * 256 + k] = l;

    if (mat == 1 && k == 0)
        g_bq[n] = (n < 128) ? boff[n] : battn[n - 128];
}

// ===========================================================================
// Pipelined bf16-split tensor-core GEMM, 64x128 tile, dual problem set.
// 8 warps = 2m x 4n, warp tile 32x32. 3 CTAs/SM target.
// Problem 1 may write fp16 output (half1 != 0); problem 2 writes fp32.
// ===========================================================================
#define LDS_BF 40
#define SM_A_HI 0
#define SM_A_LO 5120
#define SM_B(s) (10240 + (s) * 20480)
#define GEMM_SMEM 51200

__global__ void __launch_bounds__(256, 3) mma_gemm_bias2(
    const float* __restrict__ A1, const __nv_bfloat16* __restrict__ Wt1,
    const float* __restrict__ bias1, float* __restrict__ C1, int nby1, int half1,
    const float* __restrict__ A2, const __nv_bfloat16* __restrict__ Wt2,
    const float* __restrict__ bias2, float* __restrict__ C2)
{
    extern __shared__ __align__(128) char smem[];
    const uint32_t sb = smem_u32(smem);

    const int by = blockIdx.y;
    const bool p1 = (by < nby1);
    const float*         A    = p1 ? A1    : A2;
    const __nv_bfloat16* Wt   = p1 ? Wt1   : Wt2;
    const float*         bias = p1 ? bias1 : bias2;
    float*               Cout = p1 ? C1    : C2;
    const bool halfOut = p1 && half1;

    const int tid  = threadIdx.x;
    const int wid  = tid >> 5;
    const int lane = tid & 31;
    const int row0 = (p1 ? by : (by - nby1)) * 64;
    const int col0 = blockIdx.x * 128;
    const int wm   = wid & 1;
    const int wn   = wid >> 1;

    float acc[2][4][4];
    #pragma unroll
    for (int i = 0; i < 2; i++)
        #pragma unroll
        for (int j = 0; j < 4; j++)
            #pragma unroll
            for (int r = 0; r < 4; r++) acc[i][j][r] = 0.0f;

    const int a_row    = lane & 15;
    const int a_koff   = (lane >> 4) << 3;
    const int b_rowsel = lane & 7;
    const int b_koff   = ((lane >> 3) & 1) << 3;
    const int b_noff   = (lane >> 4) << 3;

    auto issueB = [&](int k0, int st) {
        #pragma unroll
        for (int i = 0; i < 4; i++) {
            int e   = tid + (i << 8);
            int buf = e >> 9;
            int r   = (e >> 2) & 127;
            int q16 = e & 3;
            const __nv_bfloat16* src =
                Wt + (size_t)buf * 65536 + (size_t)(col0 + r) * 256 + k0 + (q16 << 3);
            uint32_t dst = sb + SM_B(st) + buf * 10240 + r * 80 + (q16 << 4);
            CP_ASYNC16(dst, src);
        }
    };

    // Prologue: A chunk 0 (64 rows x 32 k = 512 float4s -> 2/thread)
    float4 aReg[2];
    #pragma unroll
    for (int i = 0; i < 2; i++) {
        int e = tid + (i << 8);
        int r = e >> 3;
        int kk = (e & 7) << 2;
        aReg[i] = *reinterpret_cast<const float4*>(A + (size_t)(row0 + r) * 256 + kk);
    }
    issueB(0, 0);
    CP_COMMIT();

    for (int c = 0; c < 8; c++) {
        if (c) __syncthreads();

        #pragma unroll
        for (int i = 0; i < 2; i++) {
            int e = tid + (i << 8);
            int r = e >> 3;
            int kk = (e & 7) << 2;
            uint32_t h0, h1, l0, l1;
            split4(aReg[i], h0, h1, l0, l1);
            uint32_t off = (uint32_t)(r * LDS_BF + kk) * 2;
            *reinterpret_cast<uint2*>(smem + SM_A_HI + off) = make_uint2(h0, h1);
            *reinterpret_cast<uint2*>(smem + SM_A_LO + off) = make_uint2(l0, l1);
        }

        if (c < 7) {
            const int k0n = (c + 1) << 5;
            #pragma unroll
            for (int i = 0; i < 2; i++) {
                int e = tid + (i << 8);
                int r = e >> 3;
                int kk = (e & 7) << 2;
                aReg[i] = *reinterpret_cast<const float4*>(
                    A + (size_t)(row0 + r) * 256 + k0n + kk);
            }
            issueB(k0n, (c + 1) & 1);
            CP_COMMIT();
            CP_WAIT1();
        } else {
            CP_WAIT0();
        }
        __syncthreads();

        const uint32_t uAhi = sb + SM_A_HI;
        const uint32_t uAlo = sb + SM_A_LO;
        const uint32_t uBhi = sb + SM_B(c & 1);
        const uint32_t uBlo = uBhi + 10240;

        #pragma unroll
        for (int ks = 0; ks < 2; ks++) {
            const int kb = ks << 4;

            uint32_t ah[2][4], bh[2][4], bl[2][4];
            #pragma unroll
            for (int mi = 0; mi < 2; mi++) {
                uint32_t addr = uAhi + (uint32_t)((wm * 32 + mi * 16 + a_row) * LDS_BF + kb + a_koff) * 2;
                ldm_x4(ah[mi], addr);
            }
            #pragma unroll
            for (int g = 0; g < 2; g++) {
                uint32_t roff = (uint32_t)((wn * 32 + g * 16 + b_noff + b_rowsel) * LDS_BF + kb + b_koff) * 2;
                ldm_x4(bh[g], uBhi + roff);
                ldm_x4(bl[g], uBlo + roff);
            }
            #pragma unroll
            for (int mi = 0; mi < 2; mi++)
                #pragma unroll
                for (int ni = 0; ni < 4; ni++) {
                    const uint32_t* bb = bh[ni >> 1];
                    mma16816(acc[mi][ni], ah[mi], bb[(ni & 1) * 2], bb[(ni & 1) * 2 + 1]);
                }
            #pragma unroll
            for (int mi = 0; mi < 2; mi++)
                #pragma unroll
                for (int ni = 0; ni < 4; ni++) {
                    const uint32_t* bb = bl[ni >> 1];
                    mma16816(acc[mi][ni], ah[mi], bb[(ni & 1) * 2], bb[(ni & 1) * 2 + 1]);
                }
            #pragma unroll
            for (int mi = 0; mi < 2; mi++) {
                uint32_t addr = uAlo + (uint32_t)((wm * 32 + mi * 16 + a_row) * LDS_BF + kb + a_koff) * 2;
                ldm_x4(ah[mi], addr);
            }
            #pragma unroll
            for (int mi = 0; mi < 2; mi++)
                #pragma unroll
                for (int ni = 0; ni < 4; ni++) {
                    const uint32_t* bb = bh[ni >> 1];
                    mma16816(acc[mi][ni], ah[mi], bb[(ni & 1) * 2], bb[(ni & 1) * 2 + 1]);
                }
        }
    }

    const int grp   = lane >> 2;
    const int cpair = (lane & 3) << 1;
    if (halfOut) {
        __half* Ch = (__half*)Cout;
        #pragma unroll
        for (int mi = 0; mi < 2; mi++) {
            #pragma unroll
            for (int ni = 0; ni < 4; ni++) {
                int colg = col0 + wn * 32 + ni * 8 + cpair;
                float b0 = bias[colg], b1 = bias[colg + 1];
                int rowg = row0 + wm * 32 + mi * 16 + grp;
                __half2 o0 = __floats2half2_rn(acc[mi][ni][0] + b0, acc[mi][ni][1] + b1);
                __half2 o1 = __floats2half2_rn(acc[mi][ni][2] + b0, acc[mi][ni][3] + b1);
                *reinterpret_cast<__half2*>(Ch + (size_t)rowg * 256 + colg) = o0;
                *reinterpret_cast<__half2*>(Ch + (size_t)(rowg + 8) * 256 + colg) = o1;
            }
        }
    } else {
        #pragma unroll
        for (int mi = 0; mi < 2; mi++) {
            #pragma unroll
            for (int ni = 0; ni < 4; ni++) {
                int colg = col0 + wn * 32 + ni * 8 + cpair;
                float b0 = bias[colg], b1 = bias[colg + 1];
                int rowg = row0 + wm * 32 + mi * 16 + grp;
                float2 o0 = make_float2(acc[mi][ni][0] + b0, acc[mi][ni][1] + b1);
                float2 o1 = make_float2(acc[mi][ni][2] + b0, acc[mi][ni][3] + b1);
                *reinterpret_cast<float2*>(Cout + (size_t)rowg * 256 + colg) = o0;
                *reinterpret_cast<float2*>(Cout + (size_t)(rowg + 8) * 256 + colg) = o1;
            }
        }
    }
}

// ---------------------------------------------------------------------------
// Fused softmax + loc + deformable gather (value in fp16).
// Phase 1 (t<128): softmax, loc, index/weight precompute packed in smem.
// Phase 2 (256 thr, warp=head, lane=channel): LDS.128 + 2x LDG.U16 + cvt + fma.
// ---------------------------------------------------------------------------
__global__ __launch_bounds__(256) void deform_fused(
    const float* __restrict__ refp,
    float* __restrict__ out_loc,
    float* __restrict__ out_attn)
{
    const int q = blockIdx.x;
    const int n = q >> 11;
    const int t = threadIdx.x;

    __shared__ int4 sPack[128];

    if (t < 128) {
        const int l = (t >> 2) & 3;
        const float* row = g_offattn + (size_t)q * 256;
        float off  = row[t];
        float araw = row[128 + t];

        float mx = araw;
        #pragma unroll
        for (int d = 1; d < 16; d <<= 1)
            mx = fmaxf(mx, __shfl_xor_sync(0xffffffffu, mx, d));
        float e = __expf(araw - mx);
        float s = e;
        #pragma unroll
        for (int d = 1; d < 16; d <<= 1)
            s += __shfl_xor_sync(0xffffffffu, s, d);

        float attn = e / s;
        float loc  = refp[(size_t)q * 4 + l] + off * c_invT[l];

        out_loc [(size_t)q * 128 + t] = loc;
        out_attn[(size_t)q * 128 + t] = attn;

        const int Ti = c_tlen[l];
        const int st = c_tstart[l];
        float pos  = loc * (float)Ti - 0.5f;
        float x0f  = floorf(pos);
        float frac = pos - x0f;
        int   x0   = (int)x0f;

        float w0 = (x0 >= 0 && x0 < Ti)         ? (1.0f - frac) * attn : 0.0f;
        float w1 = (x0 + 1 >= 0 && x0 + 1 < Ti) ? frac * attn          : 0.0f;

        int i0 = min(max(x0, 0), Ti - 1) + st;
        int i1 = min(max(x0 + 1, 0), Ti - 1) + st;

        sPack[t] = make_int4(__float_as_int(w0), __float_as_int(w1),
                             i0 << 9, i1 << 9);   // byte offsets (half row = 512 B)
    }
    __syncthreads();

    const int m = t >> 5;
    const int d = t & 31;
    const char* base = (const char*)(g_value_h + (size_t)n * S * C + m * DH + d);
    const int4* pk = &sPack[m << 4];

    float acc = 0.0f;
    #pragma unroll
    for (int lp = 0; lp < 16; lp++) {
        int4 p = pk[lp];
        float v0 = __half2float(*reinterpret_cast<const __half*>(base + p.z));
        float v1 = __half2float(*reinterpret_cast<const __half*>(base + p.w));
        acc = fmaf(__int_as_float(p.x), v0, acc);
        acc = fmaf(__int_as_float(p.y), v1, acc);
    }

    g_deform[(size_t)q * C + t] = acc;
}

// ---------------------------------------------------------------------------
extern "C" void kernel_launch(void* const* d_in, const int* in_sizes, int n_in,
                              void* d_out, int out_size)
{
    const float* query  = (const float*)d_in[0];
    const float* refp   = (const float*)d_in[1];
    const float* inpf   = (const float*)d_in[2];
    const float* W_off  = (const float*)d_in[5];
    const float* b_off  = (const float*)d_in[6];
    const float* W_attn = (const float*)d_in[7];
    const float* b_attn = (const float*)d_in[8];
    const float* W_val  = (const float*)d_in[9];
    const float* b_val  = (const float*)d_in[10];
    const float* W_out  = (const float*)d_in[11];
    const float* b_out  = (const float*)d_in[12];

    float* out      = (float*)d_out;
    float* out_loc  = out + (size_t)NQ * C;
    float* out_attn = out_loc + (size_t)NQ * MLP;

    float *pOffattn, *pDeform, *pBq;
    __half *pValueH;
    __nv_bfloat16 *pWv, *pWq, *pWo;
    cudaGetSymbolAddress((void**)&pValueH,  g_value_h);
    cudaGetSymbolAddress((void**)&pOffattn, g_offattn);
    cudaGetSymbolAddress((void**)&pDeform,  g_deform);
    cudaGetSymbolAddress((void**)&pWv,      g_wv);
    cudaGetSymbolAddress((void**)&pWq,      g_wq);
    cudaGetSymbolAddress((void**)&pWo,      g_wo);
    cudaGetSymbolAddress((void**)&pBq,      g_bq);

    cudaFuncSetAttribute(mma_gemm_bias2, cudaFuncAttributeMaxDynamicSharedMemorySize, GEMM_SMEM);

    // 0) pre-convert weights
    convert_weights<<<768, 256>>>(W_val, W_off, W_attn, W_out, b_off, b_attn);

    // 1+2) value GEMM (480 x 64-row blocks, fp16 out) + off/attn GEMM (256 blocks)
    mma_gemm_bias2<<<dim3(2, 736), 256, GEMM_SMEM>>>(
        inpf, pWv, b_val, (float*)pValueH, 480, 1,
        query, pWq, pBq, pOffattn);

    // 3) fused softmax + loc + deformable gather (fp16 value)
    deform_fused<<<NQ, 256>>>(refp, out_loc, out_attn);

    // 4) out = g_deform @ W_out + b_out  (256 x 64-row blocks)
    mma_gemm_bias2<<<dim3(2, 256), 256, GEMM_SMEM>>>(
        pDeform, pWo, b_out, out, 256, 0,
        pDeform, pWo, b_out, out);
}

// round 11
// speedup vs baseline: 2.6043x; 1.0627x over previous
#include <cuda_runtime.h>
#include <cuda_bf16.h>
#include <cuda_fp16.h>
#include <cstdint>

// Problem constants (static per reference)
#define NB   8
#define LQ   2048
#define C    256
#define M    8
#define L    4
#define P    4
#define DH   32
#define S    3840
#define NQ   (NB * LQ)          // 16384
#define MLP  (M * L * P)        // 128

__device__ __constant__ int   c_tlen[4]   = {2048, 1024, 512, 256};
__device__ __constant__ int   c_tstart[4] = {0, 2048, 3072, 3584};
__device__ __constant__ float c_invT[4]   = {1.0f/2048.0f, 1.0f/1024.0f, 1.0f/512.0f, 1.0f/256.0f};

// Scratch (device globals — no allocation allowed)
__device__ __half g_value_h[NB * S * C];  // value in fp16 (consumed only by deform)
__device__ float g_offattn[NQ * 256];     // [0:128)=off raw, [128:256)=attn raw
__device__ float g_deform[NQ * C];

// Pre-converted weights: transposed (n, k=256) bf16; hi plane then lo plane
__device__ __nv_bfloat16 g_wv[2 * 256 * 256];
__device__ __nv_bfloat16 g_wq[2 * 256 * 256];
__device__ __nv_bfloat16 g_wo[2 * 256 * 256];
__device__ float         g_bq[256];

// ===========================================================================
// Helpers
// ===========================================================================
__device__ __forceinline__ uint32_t smem_u32(const void* p) {
    uint32_t a;
    asm("{ .reg .u64 t; cvta.to.shared.u64 t, %1; cvt.u32.u64 %0, t; }" : "=r"(a) : "l"(p));
    return a;
}

__device__ __forceinline__ void ldm_x4(uint32_t* r, uint32_t addr) {
    asm volatile("ldmatrix.sync.aligned.m8n8.x4.shared.b16 {%0,%1,%2,%3}, [%4];"
                 : "=r"(r[0]), "=r"(r[1]), "=r"(r[2]), "=r"(r[3]) : "r"(addr));
}

__device__ __forceinline__ void mma16816(float* c, const uint32_t* a, uint32_t b0, uint32_t b1) {
    asm volatile("mma.sync.aligned.m16n8k16.row.col.f32.bf16.bf16.f32 "
                 "{%0,%1,%2,%3}, {%4,%5,%6,%7}, {%8,%9}, {%0,%1,%2,%3};"
                 : "+f"(c[0]), "+f"(c[1]), "+f"(c[2]), "+f"(c[3])
                 : "r"(a[0]), "r"(a[1]), "r"(a[2]), "r"(a[3]), "r"(b0), "r"(b1));
}

#define CP_ASYNC16(dst, src) \
    asm volatile("cp.async.cg.shared.global [%0], [%1], 16;" :: "r"(dst), "l"(src))
#define CP_COMMIT() asm volatile("cp.async.commit_group;" ::: "memory")
#define CP_WAIT0()  asm volatile("cp.async.wait_group 0;" ::: "memory")

__device__ __forceinline__ void split4(float4 v, uint32_t& h0, uint32_t& h1,
                                       uint32_t& l0, uint32_t& l1) {
    __nv_bfloat16 a = __float2bfloat16_rn(v.x);
    __nv_bfloat16 b = __float2bfloat16_rn(v.y);
    __nv_bfloat16 c = __float2bfloat16_rn(v.z);
    __nv_bfloat16 d = __float2bfloat16_rn(v.w);
    __nv_bfloat162 H0 = __halves2bfloat162(a, b);
    __nv_bfloat162 H1 = __halves2bfloat162(c, d);
    __nv_bfloat162 L0 = __floats2bfloat162_rn(v.x - __bfloat162float(a), v.y - __bfloat162float(b));
    __nv_bfloat162 L1 = __floats2bfloat162_rn(v.z - __bfloat162float(c), v.w - __bfloat162float(d));
    h0 = *reinterpret_cast<uint32_t*>(&H0);
    h1 = *reinterpret_cast<uint32_t*>(&H1);
    l0 = *reinterpret_cast<uint32_t*>(&L0);
    l1 = *reinterpret_cast<uint32_t*>(&L1);
}

// ===========================================================================
// Weight pre-conversion
// ===========================================================================
__global__ __launch_bounds__(256) void convert_weights(
    const float* __restrict__ Wv, const float* __restrict__ Woff,
    const float* __restrict__ Wattn, const float* __restrict__ Wo,
    const float* __restrict__ boff, const float* __restrict__ battn)
{
    int idx = blockIdx.x * 256 + threadIdx.x;
    int mat = idx >> 16;
    int r   = idx & 65535;
    int n   = r >> 8;
    int k   = r & 255;

    float v;
    if (mat == 0)      v = Wv[k * 256 + n];
    else if (mat == 1) v = (n < 128) ? Woff[k * 128 + n] : Wattn[k * 128 + (n - 128)];
    else               v = Wo[k * 256 + n];

    __nv_bfloat16 h = __float2bfloat16_rn(v);
    __nv_bfloat16 l = __float2bfloat16_rn(v - __bfloat162float(h));

    __nv_bfloat16* base = (mat == 0) ? g_wv : (mat == 1) ? g_wq : g_wo;
    base[n * 256 + k]         = h;
    base[65536 + n * 256 + k] = l;

    if (mat == 1 && k == 0)
        g_bq[n] = (n < 128) ? boff[n] : battn[n - 128];
}

// ===========================================================================
// Pipelined bf16-split tensor-core GEMM, 64x128 tile, dual problem set.
// SINGLE barrier per K-chunk: A double-buffered in smem (STS safe after
// barrier(c-1) which certifies MMA(c-2) complete); B(c+1) cp.async issued
// AFTER barrier(c) (certifies MMA(c-1) complete) and overlaps all of MMA(c).
// ===========================================================================
#define LDS_BF 40
#define SM_A(s) ((s) * 10240)            // planes: hi +0, lo +5120
#define SM_B(s) (20480 + (s) * 20480)    // planes: hi +0, lo +10240
#define GEMM_SMEM 61440

__global__ void __launch_bounds__(256, 3) mma_gemm_bias2(
    const float* __restrict__ A1, const __nv_bfloat16* __restrict__ Wt1,
    const float* __restrict__ bias1, float* __restrict__ C1, int nby1, int half1,
    const float* __restrict__ A2, const __nv_bfloat16* __restrict__ Wt2,
    const float* __restrict__ bias2, float* __restrict__ C2)
{
    extern __shared__ __align__(128) char smem[];
    const uint32_t sb = smem_u32(smem);

    const int by = blockIdx.y;
    const bool p1 = (by < nby1);
    const float*         A    = p1 ? A1    : A2;
    const __nv_bfloat16* Wt   = p1 ? Wt1   : Wt2;
    const float*         bias = p1 ? bias1 : bias2;
    float*               Cout = p1 ? C1    : C2;
    const bool halfOut = p1 && half1;

    const int tid  = threadIdx.x;
    const int wid  = tid >> 5;
    const int lane = tid & 31;
    const int row0 = (p1 ? by : (by - nby1)) * 64;
    const int col0 = blockIdx.x * 128;
    const int wm   = wid & 1;
    const int wn   = wid >> 1;

    float acc[2][4][4];
    #pragma unroll
    for (int i = 0; i < 2; i++)
        #pragma unroll
        for (int j = 0; j < 4; j++)
            #pragma unroll
            for (int r = 0; r < 4; r++) acc[i][j][r] = 0.0f;

    const int a_row    = lane & 15;
    const int a_koff   = (lane >> 4) << 3;
    const int b_rowsel = lane & 7;
    const int b_koff   = ((lane >> 3) & 1) << 3;
    const int b_noff   = (lane >> 4) << 3;

    auto issueB = [&](int k0, int st) {
        #pragma unroll
        for (int i = 0; i < 4; i++) {
            int e   = tid + (i << 8);
            int buf = e >> 9;
            int r   = (e >> 2) & 127;
            int q16 = e & 3;
            const __nv_bfloat16* src =
                Wt + (size_t)buf * 65536 + (size_t)(col0 + r) * 256 + k0 + (q16 << 3);
            uint32_t dst = sb + SM_B(st) + buf * 10240 + r * 80 + (q16 << 4);
            CP_ASYNC16(dst, src);
        }
    };

    // Prologue: A chunk 0 -> regs, B chunk 0 -> stage 0
    float4 aReg[2];
    #pragma unroll
    for (int i = 0; i < 2; i++) {
        int e = tid + (i << 8);
        int r = e >> 3;
        int kk = (e & 7) << 2;
        aReg[i] = *reinterpret_cast<const float4*>(A + (size_t)(row0 + r) * 256 + kk);
    }
    issueB(0, 0);
    CP_COMMIT();

    for (int c = 0; c < 8; c++) {
        // Split + store A(c) into bufA[c&1] (safe: barrier(c-1) passed => MMA(c-2) done)
        const uint32_t aBase = sb + SM_A(c & 1);
        #pragma unroll
        for (int i = 0; i < 2; i++) {
            int e = tid + (i << 8);
            int r = e >> 3;
            int kk = (e & 7) << 2;
            uint32_t h0, h1, l0, l1;
            split4(aReg[i], h0, h1, l0, l1);
            uint32_t off = (uint32_t)(r * LDS_BF + kk) * 2;
            *reinterpret_cast<uint2*>(smem + SM_A(c & 1) + off)        = make_uint2(h0, h1);
            *reinterpret_cast<uint2*>(smem + SM_A(c & 1) + 5120 + off) = make_uint2(l0, l1);
        }

        // Prefetch A(c+1) into regs (independent, hidden under MMA)
        if (c < 7) {
            const int k0n = (c + 1) << 5;
            #pragma unroll
            for (int i = 0; i < 2; i++) {
                int e = tid + (i << 8);
                int r = e >> 3;
                int kk = (e & 7) << 2;
                aReg[i] = *reinterpret_cast<const float4*>(
                    A + (size_t)(row0 + r) * 256 + k0n + kk);
            }
        }

        CP_WAIT0();          // B(c) landed (only group in flight)
        __syncthreads();     // A(c)+B(c) visible; all warps done MMA(c-1)

        // Issue B(c+1) AFTER barrier -> overwrite of bufB[(c+1)&1] is safe,
        // and the load overlaps the entire MMA(c) phase.
        if (c < 7) {
            issueB((c + 1) << 5, (c + 1) & 1);
            CP_COMMIT();
        }

        const uint32_t uAhi = aBase;
        const uint32_t uAlo = aBase + 5120;
        const uint32_t uBhi = sb + SM_B(c & 1);
        const uint32_t uBlo = uBhi + 10240;

        #pragma unroll
        for (int ks = 0; ks < 2; ks++) {
            const int kb = ks << 4;

            uint32_t ah[2][4], bh[2][4], bl[2][4];
            #pragma unroll
            for (int mi = 0; mi < 2; mi++) {
                uint32_t addr = uAhi + (uint32_t)((wm * 32 + mi * 16 + a_row) * LDS_BF + kb + a_koff) * 2;
                ldm_x4(ah[mi], addr);
            }
            #pragma unroll
            for (int g = 0; g < 2; g++) {
                uint32_t roff = (uint32_t)((wn * 32 + g * 16 + b_noff + b_rowsel) * LDS_BF + kb + b_koff) * 2;
                ldm_x4(bh[g], uBhi + roff);
                ldm_x4(bl[g], uBlo + roff);
            }
            #pragma unroll
            for (int mi = 0; mi < 2; mi++)
                #pragma unroll
                for (int ni = 0; ni < 4; ni++) {
                    const uint32_t* bb = bh[ni >> 1];
                    mma16816(acc[mi][ni], ah[mi], bb[(ni & 1) * 2], bb[(ni & 1) * 2 + 1]);
                }
            #pragma unroll
            for (int mi = 0; mi < 2; mi++)
                #pragma unroll
                for (int ni = 0; ni < 4; ni++) {
                    const uint32_t* bb = bl[ni >> 1];
                    mma16816(acc[mi][ni], ah[mi], bb[(ni & 1) * 2], bb[(ni & 1) * 2 + 1]);
                }
            #pragma unroll
            for (int mi = 0; mi < 2; mi++) {
                uint32_t addr = uAlo + (uint32_t)((wm * 32 + mi * 16 + a_row) * LDS_BF + kb + a_koff) * 2;
                ldm_x4(ah[mi], addr);
            }
            #pragma unroll
            for (int mi = 0; mi < 2; mi++)
                #pragma unroll
                for (int ni = 0; ni < 4; ni++) {
                    const uint32_t* bb = bh[ni >> 1];
                    mma16816(acc[mi][ni], ah[mi], bb[(ni & 1) * 2], bb[(ni & 1) * 2 + 1]);
                }
        }
    }

    const int grp   = lane >> 2;
    const int cpair = (lane & 3) << 1;
    if (halfOut) {
        __half* Ch = (__half*)Cout;
        #pragma unroll
        for (int mi = 0; mi < 2; mi++) {
            #pragma unroll
            for (int ni = 0; ni < 4; ni++) {
                int colg = col0 + wn * 32 + ni * 8 + cpair;
                float b0 = bias[colg], b1 = bias[colg + 1];
                int rowg = row0 + wm * 32 + mi * 16 + grp;
                __half2 o0 = __floats2half2_rn(acc[mi][ni][0] + b0, acc[mi][ni][1] + b1);
                __half2 o1 = __floats2half2_rn(acc[mi][ni][2] + b0, acc[mi][ni][3] + b1);
                *reinterpret_cast<__half2*>(Ch + (size_t)rowg * 256 + colg) = o0;
                *reinterpret_cast<__half2*>(Ch + (size_t)(rowg + 8) * 256 + colg) = o1;
            }
        }
    } else {
        #pragma unroll
        for (int mi = 0; mi < 2; mi++) {
            #pragma unroll
            for (int ni = 0; ni < 4; ni++) {
                int colg = col0 + wn * 32 + ni * 8 + cpair;
                float b0 = bias[colg], b1 = bias[colg + 1];
                int rowg = row0 + wm * 32 + mi * 16 + grp;
                float2 o0 = make_float2(acc[mi][ni][0] + b0, acc[mi][ni][1] + b1);
                float2 o1 = make_float2(acc[mi][ni][2] + b0, acc[mi][ni][3] + b1);
                *reinterpret_cast<float2*>(Cout + (size_t)rowg * 256 + colg) = o0;
                *reinterpret_cast<float2*>(Cout + (size_t)(rowg + 8) * 256 + colg) = o1;
            }
        }
    }
}

// ---------------------------------------------------------------------------
// Fused softmax + loc + deformable gather, TWO queries per block.
// Phase 1 (all 256 thr, one per (query-half, head, point)): softmax, loc,
// index/weight precompute packed in smem. Phase 2: loop both queries,
// warp=head, lane=channel: LDS.128 + 2x LDG.U16 + fma.
// ---------------------------------------------------------------------------
__global__ __launch_bounds__(256) void deform_fused(
    const float* __restrict__ refp,
    float* __restrict__ out_loc,
    float* __restrict__ out_attn)
{
    const int q0 = blockIdx.x << 1;
    const int n  = q0 >> 11;
    const int t  = threadIdx.x;

    __shared__ int4 sPack[256];

    {
        const int q  = q0 + (t >> 7);
        const int tt = t & 127;
        const int l  = (tt >> 2) & 3;
        const float* row = g_offattn + (size_t)q * 256;
        float off  = row[tt];
        float araw = row[128 + tt];

        float mx = araw;
        #pragma unroll
        for (int d = 1; d < 16; d <<= 1)
            mx = fmaxf(mx, __shfl_xor_sync(0xffffffffu, mx, d));
        float e = __expf(araw - mx);
        float s = e;
        #pragma unroll
        for (int d = 1; d < 16; d <<= 1)
            s += __shfl_xor_sync(0xffffffffu, s, d);

        float attn = e / s;
        float loc  = refp[(size_t)q * 4 + l] + off * c_invT[l];

        out_loc [(size_t)q * 128 + tt] = loc;
        out_attn[(size_t)q * 128 + tt] = attn;

        const int Ti = c_tlen[l];
        const int st = c_tstart[l];
        float pos  = loc * (float)Ti - 0.5f;
        float x0f  = floorf(pos);
        float frac = pos - x0f;
        int   x0   = (int)x0f;

        float w0 = (x0 >= 0 && x0 < Ti)         ? (1.0f - frac) * attn : 0.0f;
        float w1 = (x0 + 1 >= 0 && x0 + 1 < Ti) ? frac * attn          : 0.0f;

        int i0 = min(max(x0, 0), Ti - 1) + st;
        int i1 = min(max(x0 + 1, 0), Ti - 1) + st;

        sPack[t] = make_int4(__float_as_int(w0), __float_as_int(w1),
                             i0 << 9, i1 << 9);   // byte offsets (half row = 512 B)
    }
    __syncthreads();

    const int m = t >> 5;
    const int d = t & 31;
    const char* base = (const char*)(g_value_h + (size_t)n * S * C + m * DH + d);

    #pragma unroll
    for (int qi = 0; qi < 2; qi++) {
        const int4* pk = &sPack[(qi << 7) + (m << 4)];
        float acc = 0.0f;
        #pragma unroll
        for (int lp = 0; lp < 16; lp++) {
            int4 p = pk[lp];
            float v0 = __half2float(*reinterpret_cast<const __half*>(base + p.z));
            float v1 = __half2float(*reinterpret_cast<const __half*>(base + p.w));
            acc = fmaf(__int_as_float(p.x), v0, acc);
            acc = fmaf(__int_as_float(p.y), v1, acc);
        }
        g_deform[(size_t)(q0 + qi) * C + t] = acc;
    }
}

// ---------------------------------------------------------------------------
extern "C" void kernel_launch(void* const* d_in, const int* in_sizes, int n_in,
                              void* d_out, int out_size)
{
    const float* query  = (const float*)d_in[0];
    const float* refp   = (const float*)d_in[1];
    const float* inpf   = (const float*)d_in[2];
    const float* W_off  = (const float*)d_in[5];
    const float* b_off  = (const float*)d_in[6];
    const float* W_attn = (const float*)d_in[7];
    const float* b_attn = (const float*)d_in[8];
    const float* W_val  = (const float*)d_in[9];
    const float* b_val  = (const float*)d_in[10];
    const float* W_out  = (const float*)d_in[11];
    const float* b_out  = (const float*)d_in[12];

    float* out      = (float*)d_out;
    float* out_loc  = out + (size_t)NQ * C;
    float* out_attn = out_loc + (size_t)NQ * MLP;

    float *pOffattn, *pDeform, *pBq;
    __half *pValueH;
    __nv_bfloat16 *pWv, *pWq, *pWo;
    cudaGetSymbolAddress((void**)&pValueH,  g_value_h);
    cudaGetSymbolAddress((void**)&pOffattn, g_offattn);
    cudaGetSymbolAddress((void**)&pDeform,  g_deform);
    cudaGetSymbolAddress((void**)&pWv,      g_wv);
    cudaGetSymbolAddress((void**)&pWq,      g_wq);
    cudaGetSymbolAddress((void**)&pWo,      g_wo);
    cudaGetSymbolAddress((void**)&pBq,      g_bq);

    cudaFuncSetAttribute(mma_gemm_bias2, cudaFuncAttributeMaxDynamicSharedMemorySize, GEMM_SMEM);

    // 0) pre-convert weights
    convert_weights<<<768, 256>>>(W_val, W_off, W_attn, W_out, b_off, b_attn);

    // 1+2) value GEMM (480 x 64-row blocks, fp16 out) + off/attn GEMM (256 blocks)
    mma_gemm_bias2<<<dim3(2, 736), 256, GEMM_SMEM>>>(
        inpf, pWv, b_val, (float*)pValueH, 480, 1,
        query, pWq, pBq, pOffattn);

    // 3) fused softmax + loc + deformable gather (fp16 value, 2 queries/block)
    deform_fused<<<NQ / 2, 256>>>(refp, out_loc, out_attn);

    // 4) out = g_deform @ W_out + b_out  (256 x 64-row blocks)
    mma_gemm_bias2<<<dim3(2, 256), 256, GEMM_SMEM>>>(
        pDeform, pWo, b_out, out, 256, 0,
        pDeform, pWo, b_out, out);
}

// round 12
// speedup vs baseline: 2.9575x; 1.1356x over previous
#include <cuda_runtime.h>
#include <cuda_bf16.h>
#include <cuda_fp16.h>
#include <cstdint>

// Problem constants (static per reference)
#define NB   8
#define LQ   2048
#define C    256
#define M    8
#define L    4
#define P    4
#define DH   32
#define S    3840
#define NQ   (NB * LQ)          // 16384
#define MLP  (M * L * P)        // 128

__device__ __constant__ int   c_tlen[4]   = {2048, 1024, 512, 256};
__device__ __constant__ int   c_tstart[4] = {0, 2048, 3072, 3584};
__device__ __constant__ float c_invT[4]   = {1.0f/2048.0f, 1.0f/1024.0f, 1.0f/512.0f, 1.0f/256.0f};

// Scratch (device globals — no allocation allowed)
__device__ __half g_value_h[NB * S * C];  // value in fp16 (consumed only by deform)
__device__ float g_offattn[NQ * 256];     // [0:128)=off raw, [128:256)=attn raw
__device__ float g_deform[NQ * C];

// Pre-converted weights: transposed (n, k=256) fp16; hi plane then lo plane
__device__ __half g_wv[2 * 256 * 256];
__device__ __half g_wq[2 * 256 * 256];
__device__ __half g_wo[2 * 256 * 256];
__device__ float  g_bq[256];

// ===========================================================================
// Helpers
// ===========================================================================
__device__ __forceinline__ uint32_t smem_u32(const void* p) {
    uint32_t a;
    asm("{ .reg .u64 t; cvta.to.shared.u64 t, %1; cvt.u32.u64 %0, t; }" : "=r"(a) : "l"(p));
    return a;
}

__device__ __forceinline__ void ldm_x4(uint32_t* r, uint32_t addr) {
    asm volatile("ldmatrix.sync.aligned.m8n8.x4.shared.b16 {%0,%1,%2,%3}, [%4];"
                 : "=r"(r[0]), "=r"(r[1]), "=r"(r[2]), "=r"(r[3]) : "r"(addr));
}

__device__ __forceinline__ void mma16816(float* c, const uint32_t* a, uint32_t b0, uint32_t b1) {
    asm volatile("mma.sync.aligned.m16n8k16.row.col.f32.f16.f16.f32 "
                 "{%0,%1,%2,%3}, {%4,%5,%6,%7}, {%8,%9}, {%0,%1,%2,%3};"
                 : "+f"(c[0]), "+f"(c[1]), "+f"(c[2]), "+f"(c[3])
                 : "r"(a[0]), "r"(a[1]), "r"(a[2]), "r"(a[3]), "r"(b0), "r"(b1));
}

#define CP_ASYNC16(dst, src) \
    asm volatile("cp.async.cg.shared.global [%0], [%1], 16;" :: "r"(dst), "l"(src))
#define CP_COMMIT() asm volatile("cp.async.commit_group;" ::: "memory")
#define CP_WAIT0()  asm volatile("cp.async.wait_group 0;" ::: "memory")

// ===========================================================================
// Weight pre-conversion: W (k-major fp32) -> W^T (n,256) fp16 hi + fp16 lo.
// ===========================================================================
__global__ __launch_bounds__(256) void convert_weights(
    const float* __restrict__ Wv, const float* __restrict__ Woff,
    const float* __restrict__ Wattn, const float* __restrict__ Wo,
    const float* __restrict__ boff, const float* __restrict__ battn)
{
    int idx = blockIdx.x * 256 + threadIdx.x;
    int mat = idx >> 16;
    int r   = idx & 65535;
    int n   = r >> 8;
    int k   = r & 255;

    float v;
    if (mat == 0)      v = Wv[k * 256 + n];
    else if (mat == 1) v = (n < 128) ? Woff[k * 128 + n] : Wattn[k * 128 + (n - 128)];
    else               v = Wo[k * 256 + n];

    __half h = __float2half_rn(v);
    __half l = __float2half_rn(v - __half2float(h));

    __half* base = (mat == 0) ? g_wv : (mat == 1) ? g_wq : g_wo;
    base[n * 256 + k]         = h;
    base[65536 + n * 256 + k] = l;

    if (mat == 1 && k == 0)
        g_bq[n] = (n < 128) ? boff[n] : battn[n - 128];
}

// ===========================================================================
// Pipelined fp16 2-term tensor-core GEMM, 64x128 tile, dual problem set.
// C = A @ W + bias computed as A_f16 @ (W_hi + W_lo): dropped a_lo*b term
// is ~2^-12 relative. A: single fp16 plane, cvt in-flight, double-buffered.
// B: hi/lo planes via cp.async double buffer. ONE barrier per K-chunk.
// ===========================================================================
#define LDS_BF 40
#define SM_A(s) ((s) * 5120)             // single fp16 plane, 64 x 80 B
#define SM_B(s) (10240 + (s) * 20480)    // planes: hi +0, lo +10240
#define GEMM_SMEM 51200

__global__ void __launch_bounds__(256, 3) mma_gemm_bias2(
    const float* __restrict__ A1, const __half* __restrict__ Wt1,
    const float* __restrict__ bias1, float* __restrict__ C1, int nby1, int half1,
    const float* __restrict__ A2, const __half* __restrict__ Wt2,
    const float* __restrict__ bias2, float* __restrict__ C2)
{
    extern __shared__ __align__(128) char smem[];
    const uint32_t sb = smem_u32(smem);

    const int by = blockIdx.y;
    const bool p1 = (by < nby1);
    const float*  A    = p1 ? A1    : A2;
    const __half* Wt   = p1 ? Wt1   : Wt2;
    const float*  bias = p1 ? bias1 : bias2;
    float*        Cout = p1 ? C1    : C2;
    const bool halfOut = p1 && half1;

    const int tid  = threadIdx.x;
    const int wid  = tid >> 5;
    const int lane = tid & 31;
    const int row0 = (p1 ? by : (by - nby1)) * 64;
    const int col0 = blockIdx.x * 128;
    const int wm   = wid & 1;
    const int wn   = wid >> 1;

    float acc[2][4][4];
    #pragma unroll
    for (int i = 0; i < 2; i++)
        #pragma unroll
        for (int j = 0; j < 4; j++)
            #pragma unroll
            for (int r = 0; r < 4; r++) acc[i][j][r] = 0.0f;

    const int a_row    = lane & 15;
    const int a_koff   = (lane >> 4) << 3;
    const int b_rowsel = lane & 7;
    const int b_koff   = ((lane >> 3) & 1) << 3;
    const int b_noff   = (lane >> 4) << 3;

    auto issueB = [&](int k0, int st) {
        #pragma unroll
        for (int i = 0; i < 4; i++) {
            int e   = tid + (i << 8);
            int buf = e >> 9;
            int r   = (e >> 2) & 127;
            int q16 = e & 3;
            const __half* src =
                Wt + (size_t)buf * 65536 + (size_t)(col0 + r) * 256 + k0 + (q16 << 3);
            uint32_t dst = sb + SM_B(st) + buf * 10240 + r * 80 + (q16 << 4);
            CP_ASYNC16(dst, src);
        }
    };

    // Prologue: A chunk 0 -> regs, B chunk 0 -> stage 0
    float4 aReg[2];
    #pragma unroll
    for (int i = 0; i < 2; i++) {
        int e = tid + (i << 8);
        int r = e >> 3;
        int kk = (e & 7) << 2;
        aReg[i] = *reinterpret_cast<const float4*>(A + (size_t)(row0 + r) * 256 + kk);
    }
    issueB(0, 0);
    CP_COMMIT();

    for (int c = 0; c < 8; c++) {
        // cvt + store A(c) into bufA[c&1]
        const uint32_t aBase = sb + SM_A(c & 1);
        #pragma unroll
        for (int i = 0; i < 2; i++) {
            int e = tid + (i << 8);
            int r = e >> 3;
            int kk = (e & 7) << 2;
            __half2 p0 = __floats2half2_rn(aReg[i].x, aReg[i].y);
            __half2 p1 = __floats2half2_rn(aReg[i].z, aReg[i].w);
            uint32_t off = (uint32_t)(r * LDS_BF + kk) * 2;
            *reinterpret_cast<uint2*>(smem + SM_A(c & 1) + off) =
                make_uint2(*reinterpret_cast<uint32_t*>(&p0),
                           *reinterpret_cast<uint32_t*>(&p1));
        }

        // Prefetch A(c+1) into regs (hidden under MMA)
        if (c < 7) {
            const int k0n = (c + 1) << 5;
            #pragma unroll
            for (int i = 0; i < 2; i++) {
                int e = tid + (i << 8);
                int r = e >> 3;
                int kk = (e & 7) << 2;
                aReg[i] = *reinterpret_cast<const float4*>(
                    A + (size_t)(row0 + r) * 256 + k0n + kk);
            }
        }

        CP_WAIT0();          // B(c) landed
        __syncthreads();     // A(c)+B(c) visible; all warps done MMA(c-1)

        // Issue B(c+1) after the barrier; overlaps all of MMA(c)
        if (c < 7) {
            issueB((c + 1) << 5, (c + 1) & 1);
            CP_COMMIT();
        }

        const uint32_t uA   = aBase;
        const uint32_t uBhi = sb + SM_B(c & 1);
        const uint32_t uBlo = uBhi + 10240;

        #pragma unroll
        for (int ks = 0; ks < 2; ks++) {
            const int kb = ks << 4;

            uint32_t ah[2][4], bh[2][4], bl[2][4];
            #pragma unroll
            for (int mi = 0; mi < 2; mi++) {
                uint32_t addr = uA + (uint32_t)((wm * 32 + mi * 16 + a_row) * LDS_BF + kb + a_koff) * 2;
                ldm_x4(ah[mi], addr);
            }
            #pragma unroll
            for (int g = 0; g < 2; g++) {
                uint32_t roff = (uint32_t)((wn * 32 + g * 16 + b_noff + b_rowsel) * LDS_BF + kb + b_koff) * 2;
                ldm_x4(bh[g], uBhi + roff);
                ldm_x4(bl[g], uBlo + roff);
            }
            // term 1: A * B_hi
            #pragma unroll
            for (int mi = 0; mi < 2; mi++)
                #pragma unroll
                for (int ni = 0; ni < 4; ni++) {
                    const uint32_t* bb = bh[ni >> 1];
                    mma16816(acc[mi][ni], ah[mi], bb[(ni & 1) * 2], bb[(ni & 1) * 2 + 1]);
                }
            // term 2: A * B_lo
            #pragma unroll
            for (int mi = 0; mi < 2; mi++)
                #pragma unroll
                for (int ni = 0; ni < 4; ni++) {
                    const uint32_t* bb = bl[ni >> 1];
                    mma16816(acc[mi][ni], ah[mi], bb[(ni & 1) * 2], bb[(ni & 1) * 2 + 1]);
                }
        }
    }

    const int grp   = lane >> 2;
    const int cpair = (lane & 3) << 1;
    if (halfOut) {
        __half* Ch = (__half*)Cout;
        #pragma unroll
        for (int mi = 0; mi < 2; mi++) {
            #pragma unroll
            for (int ni = 0; ni < 4; ni++) {
                int colg = col0 + wn * 32 + ni * 8 + cpair;
                float b0 = bias[colg], b1 = bias[colg + 1];
                int rowg = row0 + wm * 32 + mi * 16 + grp;
                __half2 o0 = __floats2half2_rn(acc[mi][ni][0] + b0, acc[mi][ni][1] + b1);
                __half2 o1 = __floats2half2_rn(acc[mi][ni][2] + b0, acc[mi][ni][3] + b1);
                *reinterpret_cast<__half2*>(Ch + (size_t)rowg * 256 + colg) = o0;
                *reinterpret_cast<__half2*>(Ch + (size_t)(rowg + 8) * 256 + colg) = o1;
            }
        }
    } else {
        #pragma unroll
        for (int mi = 0; mi < 2; mi++) {
            #pragma unroll
            for (int ni = 0; ni < 4; ni++) {
                int colg = col0 + wn * 32 + ni * 8 + cpair;
                float b0 = bias[colg], b1 = bias[colg + 1];
                int rowg = row0 + wm * 32 + mi * 16 + grp;
                float2 o0 = make_float2(acc[mi][ni][0] + b0, acc[mi][ni][1] + b1);
                float2 o1 = make_float2(acc[mi][ni][2] + b0, acc[mi][ni][3] + b1);
                *reinterpret_cast<float2*>(Cout + (size_t)rowg * 256 + colg) = o0;
                *reinterpret_cast<float2*>(Cout + (size_t)(rowg + 8) * 256 + colg) = o1;
            }
        }
    }
}

// ---------------------------------------------------------------------------
// Fused softmax + loc + deformable gather, TWO queries per block.
// ---------------------------------------------------------------------------
__global__ __launch_bounds__(256) void deform_fused(
    const float* __restrict__ refp,
    float* __restrict__ out_loc,
    float* __restrict__ out_attn)
{
    const int q0 = blockIdx.x << 1;
    const int n  = q0 >> 11;
    const int t  = threadIdx.x;

    __shared__ int4 sPack[256];

    {
        const int q  = q0 + (t >> 7);
        const int tt = t & 127;
        const int l  = (tt >> 2) & 3;
        const float* row = g_offattn + (size_t)q * 256;
        float off  = row[tt];
        float araw = row[128 + tt];

        float mx = araw;
        #pragma unroll
        for (int d = 1; d < 16; d <<= 1)
            mx = fmaxf(mx, __shfl_xor_sync(0xffffffffu, mx, d));
        float e = __expf(araw - mx);
        float s = e;
        #pragma unroll
        for (int d = 1; d < 16; d <<= 1)
            s += __shfl_xor_sync(0xffffffffu, s, d);

        float attn = e / s;
        float loc  = refp[(size_t)q * 4 + l] + off * c_invT[l];

        out_loc [(size_t)q * 128 + tt] = loc;
        out_attn[(size_t)q * 128 + tt] = attn;

        const int Ti = c_tlen[l];
        const int st = c_tstart[l];
        float pos  = loc * (float)Ti - 0.5f;
        float x0f  = floorf(pos);
        float frac = pos - x0f;
        int   x0   = (int)x0f;

        float w0 = (x0 >= 0 && x0 < Ti)         ? (1.0f - frac) * attn : 0.0f;
        float w1 = (x0 + 1 >= 0 && x0 + 1 < Ti) ? frac * attn          : 0.0f;

        int i0 = min(max(x0, 0), Ti - 1) + st;
        int i1 = min(max(x0 + 1, 0), Ti - 1) + st;

        sPack[t] = make_int4(__float_as_int(w0), __float_as_int(w1),
                             i0 << 9, i1 << 9);   // byte offsets (half row = 512 B)
    }
    __syncthreads();

    const int m = t >> 5;
    const int d = t & 31;
    const char* base = (const char*)(g_value_h + (size_t)n * S * C + m * DH + d);

    #pragma unroll
    for (int qi = 0; qi < 2; qi++) {
        const int4* pk = &sPack[(qi << 7) + (m << 4)];
        float acc = 0.0f;
        #pragma unroll
        for (int lp = 0; lp < 16; lp++) {
            int4 p = pk[lp];
            float v0 = __half2float(*reinterpret_cast<const __half*>(base + p.z));
            float v1 = __half2float(*reinterpret_cast<const __half*>(base + p.w));
            acc = fmaf(__int_as_float(p.x), v0, acc);
            acc = fmaf(__int_as_float(p.y), v1, acc);
        }
        g_deform[(size_t)(q0 + qi) * C + t] = acc;
    }
}

// ---------------------------------------------------------------------------
extern "C" void kernel_launch(void* const* d_in, const int* in_sizes, int n_in,
                              void* d_out, int out_size)
{
    const float* query  = (const float*)d_in[0];
    const float* refp   = (const float*)d_in[1];
    const float* inpf   = (const float*)d_in[2];
    const float* W_off  = (const float*)d_in[5];
    const float* b_off  = (const float*)d_in[6];
    const float* W_attn = (const float*)d_in[7];
    const float* b_attn = (const float*)d_in[8];
    const float* W_val  = (const float*)d_in[9];
    const float* b_val  = (const float*)d_in[10];
    const float* W_out  = (const float*)d_in[11];
    const float* b_out  = (const float*)d_in[12];

    float* out      = (float*)d_out;
    float* out_loc  = out + (size_t)NQ * C;
    float* out_attn = out_loc + (size_t)NQ * MLP;

    float *pOffattn, *pDeform, *pBq;
    __half *pValueH, *pWv, *pWq, *pWo;
    cudaGetSymbolAddress((void**)&pValueH,  g_value_h);
    cudaGetSymbolAddress((void**)&pOffattn, g_offattn);
    cudaGetSymbolAddress((void**)&pDeform,  g_deform);
    cudaGetSymbolAddress((void**)&pWv,      g_wv);
    cudaGetSymbolAddress((void**)&pWq,      g_wq);
    cudaGetSymbolAddress((void**)&pWo,      g_wo);
    cudaGetSymbolAddress((void**)&pBq,      g_bq);

    cudaFuncSetAttribute(mma_gemm_bias2, cudaFuncAttributeMaxDynamicSharedMemorySize, GEMM_SMEM);

    // 0) pre-convert weights to fp16 hi/lo
    convert_weights<<<768, 256>>>(W_val, W_off, W_attn, W_out, b_off, b_attn);

    // 1+2) value GEMM (480 x 64-row blocks, fp16 out) + off/attn GEMM (256 blocks)
    mma_gemm_bias2<<<dim3(2, 736), 256, GEMM_SMEM>>>(
        inpf, pWv, b_val, (float*)pValueH, 480, 1,
        query, pWq, pBq, pOffattn);

    // 3) fused softmax + loc + deformable gather (fp16 value, 2 queries/block)
    deform_fused<<<NQ / 2, 256>>>(refp, out_loc, out_attn);

    // 4) out = g_deform @ W_out + b_out  (256 x 64-row blocks)
    mma_gemm_bias2<<<dim3(2, 256), 256, GEMM_SMEM>>>(
        pDeform, pWo, b_out, out, 256, 0,
        pDeform, pWo, b_out, out);
}